// round 4
// baseline (speedup 1.0000x reference)
#include <cuda_runtime.h>
#include <cuda_bf16.h>

// ---------------- problem constants ----------------
#define HN    256
#define BB    64
#define NN    4096
#define TT    100
#define GBLK  32

#define V_REST_C   (-70.0f)
#define V_RESET_C  (-75.0f)
#define V_THRESH_C (-55.0f)
// rigorous no-spike input bound: v_max - V_REST <= 5*max(0,max_input);
// spike needs input >= 3.0; use 2.9 for float slop (actual max ~1.8)
#define X_LIMIT    2.9f

// ---------------- static device scratch ----------------
__device__ float d_gA[4 * BB * NN];        // k-split partials of spikes@adj
__device__ float d_g[BB * NN];             // g = spikes@adj
__device__ float d_x0p[32 * BB * HN];      // k-split partials of g@W0
__device__ float d_x0[BB * HN];            // x0_pre = g@W0 + b0
__device__ float d_sp0[BB * HN];
__device__ float d_sp1[BB * HN];
__device__ float d_x1[BB * HN];
__device__ float d_x2[BB * HN];
__device__ unsigned d_barcount;
__device__ unsigned d_bargen;
__device__ unsigned d_need_slow;

// ---------------- f32x2 packed FMA (PTX-only; 2 IEEE-RN fp32 FMAs/slot) ----
__device__ __forceinline__ void fma2(unsigned long long& acc,
                                     unsigned long long a,
                                     unsigned long long b) {
    asm("fma.rn.f32x2 %0, %1, %2, %0;" : "+l"(acc) : "l"(a), "l"(b));
}
__device__ __forceinline__ void unpack2(unsigned long long p, float& lo, float& hi) {
    asm("mov.b64 {%0, %1}, %2;" : "=f"(lo), "=f"(hi) : "l"(p));
}

// ---------------- LIF micro-step ----------------
__device__ __forceinline__ void lif_step(float& v, float& isyn, float& refr,
                                         float ib, float& sp) {
    const bool  in_refr = refr > 0.0f;
    const float isyn_u  = isyn + (ib - isyn * 0.2f);
    const float v_u     = v + (isyn_u - (v - V_REST_C)) * 0.05f;
    const bool  spike   = (!in_refr) && (v_u >= V_THRESH_C);
    v    = in_refr ? v    : (spike ? V_RESET_C : v_u);
    isyn = in_refr ? isyn : isyn_u;
    refr = in_refr ? (refr - 1.0f) : (spike ? 2.0f : refr);
    sp   = spike ? 1.0f : 0.0f;
}

// ---------------- grid barrier ----------------
__device__ __forceinline__ void gbar() {
    __syncthreads();
    if (threadIdx.x == 0) {
        __threadfence();
        unsigned gen = *((volatile unsigned*)&d_bargen);
        if (atomicAdd(&d_barcount, 1u) == GBLK - 1u) {
            d_barcount = 0u;
            __threadfence();
            atomicAdd(&d_bargen, 1u);
        } else {
            while (*((volatile unsigned*)&d_bargen) == gen) { }
        }
        __threadfence();
    }
    __syncthreads();
}

// ---------------- f32x2 SGEMM: Cpart[gy] = A[64,Kchunk] @ B[Kchunk,N] -------
// BM=64, BN=32, BK=32; 256 threads. Thread tile 4x2 via 4 fma2/k.
// B stored DUPLICATED in shared so the broadcast operand is a direct LDS.
__global__ void __launch_bounds__(256) k_sgemm_part(
    const float* __restrict__ A, const float* __restrict__ B,
    float* __restrict__ Cp, int lda, int Kchunk, int N)
{
    __shared__ __align__(16) float As[32][64];      // [k][m]
    __shared__ __align__(16) float Bd[32][64];      // [k][2n dup]
    const int tid = threadIdx.x;
    const int n0  = blockIdx.x * 32;
    const int k0  = blockIdx.y * Kchunk;
    const int ty2 = tid >> 4;      // 0..15 -> 4 M rows
    const int tx2 = tid & 15;      // 0..15 -> 2 N cols

    unsigned long long acc[2][2] = {{0ull, 0ull}, {0ull, 0ull}};

    const int ra = tid >> 3;              // 0..31
    const int kq = (tid & 7) << 2;        // 0,4,...,28
    for (int kt = 0; kt < Kchunk; kt += 32) {
#pragma unroll
        for (int p = 0; p < 2; ++p) {
            const int r = ra + 32 * p;
            float4 av = *(const float4*)(A + (size_t)r * lda + (k0 + kt + kq));
            As[kq + 0][r] = av.x;
            As[kq + 1][r] = av.y;
            As[kq + 2][r] = av.z;
            As[kq + 3][r] = av.w;
        }
        {
            float4 bv = *(const float4*)(B + (size_t)(k0 + kt + ra) * N + (n0 + kq));
            float4 d0 = {bv.x, bv.x, bv.y, bv.y};
            float4 d1 = {bv.z, bv.z, bv.w, bv.w};
            *(float4*)&Bd[ra][2 * kq]     = d0;
            *(float4*)&Bd[ra][2 * kq + 4] = d1;
        }
        __syncthreads();
#pragma unroll 8
        for (int kk = 0; kk < 32; ++kk) {
            ulonglong2 av = *(const ulonglong2*)&As[kk][ty2 * 4];  // rows pair x2
            ulonglong2 bv = *(const ulonglong2*)&Bd[kk][tx2 * 4];  // 2 dup cols
            fma2(acc[0][0], av.x, bv.x);
            fma2(acc[0][1], av.x, bv.y);
            fma2(acc[1][0], av.y, bv.x);
            fma2(acc[1][1], av.y, bv.y);
        }
        __syncthreads();
    }
    float* C = Cp + (size_t)blockIdx.y * (64 * (size_t)N);
#pragma unroll
    for (int i = 0; i < 2; ++i) {
#pragma unroll
        for (int j = 0; j < 2; ++j) {
            float lo, hi;
            unpack2(acc[i][j], lo, hi);
            const int col = n0 + tx2 * 2 + j;
            C[(size_t)(ty2 * 4 + 2 * i + 0) * N + col] = lo;
            C[(size_t)(ty2 * 4 + 2 * i + 1) * N + col] = hi;
        }
    }
}

// g = sum of 4 partials
__global__ void __launch_bounds__(256) k_reduce_g() {
    int i = blockIdx.x * blockDim.x + threadIdx.x;
    int stride = gridDim.x * blockDim.x;
    for (; i < BB * NN; i += stride)
        d_g[i] = (d_gA[i] + d_gA[BB * NN + i]) +
                 (d_gA[2 * BB * NN + i] + d_gA[3 * BB * NN + i]);
}

// ---------------- zero traces + reset flag ----------------
__global__ void __launch_bounds__(256) k_zero_traces(float* __restrict__ traces) {
    if (blockIdx.x == 0 && threadIdx.x == 0) d_need_slow = 0u;
    const float4 z = {0.f, 0.f, 0.f, 0.f};
    float4* t4 = (float4*)traces;
    int i = blockIdx.x * blockDim.x + threadIdx.x;
    int stride = gridDim.x * blockDim.x;
    const int n4 = (TT * BB * HN) / 4;
    for (; i < n4; i += stride) t4[i] = z;
}

// ---------------- validate: reduce x0 partials + analytic no-spike checks ---
// blocks 0..63: finalize d_x0 row-chunks, check max(x0) < X_LIMIT.
// block 64: check b1, b2 (layers 1/2 see constant bias input when upstream
// is silent). Any violation -> d_need_slow=1 -> exact fallback runs.
__global__ void __launch_bounds__(256) k_validate(const float* __restrict__ b0,
                                                  const float* __restrict__ b1,
                                                  const float* __restrict__ b2)
{
    const int tid = threadIdx.x;
    int bad;
    if (blockIdx.x < 64) {
        const int i = blockIdx.x * 256 + tid;
        float s = 0.f;
#pragma unroll
        for (int p = 0; p < 32; ++p) s += d_x0p[p * (BB * HN) + i];
        s += __ldg(b0 + tid);
        d_x0[i] = s;
        bad = (s >= X_LIMIT);
    } else {
        bad = (__ldg(b1 + tid) >= X_LIMIT) || (__ldg(b2 + tid) >= X_LIMIT);
    }
    if (__syncthreads_or(bad) && tid == 0) atomicOr(&d_need_slow, 1u);
}

// ---------------- exact fallback (verified round-2 path) ----------------
__device__ __forceinline__ int stage_to_smem(const float* __restrict__ src,
                                             float* __restrict__ s_x, int tid) {
    const float4* s4 = (const float4*)src;
    float4* dd = (float4*)s_x;
    int flag = 0;
#pragma unroll
    for (int it = 0; it < 16; ++it) {
        int i = tid + it * 256;
        float4 v = __ldcg(s4 + i);
        flag |= (v.x != 0.f) | (v.y != 0.f) | (v.z != 0.f) | (v.w != 0.f);
        dd[i] = v;
    }
    return flag;
}

__device__ __forceinline__ void gemm_phase(const float* __restrict__ sp,
                                           const float* __restrict__ W,
                                           const float* __restrict__ bias,
                                           float* __restrict__ xout,
                                           int bid, int tid,
                                           float* s_rows, float* s_psum) {
    int flag = 0;
#pragma unroll
    for (int it = 0; it < 2; ++it) {
        int i = tid + it * 256;
        float v = __ldcg(sp + bid * 512 + i);
        flag |= (v != 0.f);
        s_rows[i] = v;
    }
    const int tx = tid & 63;
    const int ty = tid >> 6;
    const int c0 = tx * 4;
    const int kb = ty * 64;
    const int any = __syncthreads_or(flag);

    if (any) {
        float4 a0 = {0.f, 0.f, 0.f, 0.f}, a1 = {0.f, 0.f, 0.f, 0.f};
        const float* s0 = s_rows + kb;
        const float* s1 = s_rows + 256 + kb;
#pragma unroll 8
        for (int k = 0; k < 64; ++k) {
            float4 ww = __ldg((const float4*)(W + (size_t)(kb + k) * 256 + c0));
            float u0 = s0[k], u1 = s1[k];
            a0.x += u0 * ww.x; a0.y += u0 * ww.y; a0.z += u0 * ww.z; a0.w += u0 * ww.w;
            a1.x += u1 * ww.x; a1.y += u1 * ww.y; a1.z += u1 * ww.z; a1.w += u1 * ww.w;
        }
        *(float4*)&s_psum[(ty * 2 + 0) * 256 + c0] = a0;
        *(float4*)&s_psum[(ty * 2 + 1) * 256 + c0] = a1;
        __syncthreads();
        if (ty == 0) {
#pragma unroll
            for (int r = 0; r < 2; ++r) {
                float4 p0 = *(float4*)&s_psum[(0 + r) * 256 + c0];
                float4 p1 = *(float4*)&s_psum[(2 + r) * 256 + c0];
                float4 p2 = *(float4*)&s_psum[(4 + r) * 256 + c0];
                float4 p3 = *(float4*)&s_psum[(6 + r) * 256 + c0];
                float4 bbv = __ldg((const float4*)(bias + c0));
                float4 o;
                o.x = ((p0.x + p1.x) + (p2.x + p3.x)) + bbv.x;
                o.y = ((p0.y + p1.y) + (p2.y + p3.y)) + bbv.y;
                o.z = ((p0.z + p1.z) + (p2.z + p3.z)) + bbv.z;
                o.w = ((p0.w + p1.w) + (p2.w + p3.w)) + bbv.w;
                *(float4*)(xout + (size_t)(bid * 2 + r) * 256 + c0) = o;
            }
        }
        __syncthreads();
    } else {
        if (ty == 0) {
            float4 bbv = __ldg((const float4*)(bias + c0));
#pragma unroll
            for (int r = 0; r < 2; ++r)
                *(float4*)(xout + (size_t)(bid * 2 + r) * 256 + c0) = bbv;
        }
        __syncthreads();
    }
}

__device__ __forceinline__ void lif_scan_layer(const float* __restrict__ xin,
                                               float* __restrict__ spout,
                                               float& v, float& isyn, float& refr,
                                               int tid, float* s_x) {
    int flag = stage_to_smem(xin, s_x, tid);
    flag |= (v != V_REST_C) | (isyn != 0.f) | (refr != 0.f);
    const int any = __syncthreads_or(flag);
    if (any) {
        float nxt = s_x[tid];
#pragma unroll 4
        for (int b = 0; b < 64; ++b) {
            float ib = nxt;
            if (b < 63) nxt = s_x[(b + 1) * 256 + tid];
            float sp;
            lif_step(v, isyn, refr, ib, sp);
            spout[b * 256 + tid] = sp;
        }
    } else {
        float4 z = {0.f, 0.f, 0.f, 0.f};
        float4* o4 = (float4*)spout;
#pragma unroll
        for (int it = 0; it < 16; ++it) o4[tid + it * 256] = z;
    }
    __syncthreads();
}

__global__ void __launch_bounds__(256) k_persist_slow(
    const float* __restrict__ x0pre,
    const float* __restrict__ W1, const float* __restrict__ b1,
    const float* __restrict__ W2, const float* __restrict__ b2,
    float* __restrict__ traces)
{
    if (atomicOr(&d_need_slow, 0u) == 0u) return;

    extern __shared__ float sh[];
    float* s_x    = sh;
    float* s_rows = sh + 16384;
    float* s_psum = sh + 16896;
    const int tid = threadIdx.x;
    const int bid = blockIdx.x;

    float v0 = V_REST_C, i0 = 0.f, r0 = 0.f;
    float v1 = V_REST_C, i1 = 0.f, r1 = 0.f;
    float v2 = V_REST_C, i2 = 0.f, r2 = 0.f;

    for (int t = 0; t < TT; ++t) {
        if (bid == 0) {
            float nxt = __ldg(x0pre + tid);
#pragma unroll 4
            for (int b = 0; b < 64; ++b) {
                float ib = nxt;
                if (b < 63) nxt = __ldg(x0pre + (b + 1) * 256 + tid);
                float sp;
                lif_step(v0, i0, r0, ib, sp);
                d_sp0[b * 256 + tid] = sp;
            }
        }
        gbar();
        gemm_phase(d_sp0, W1, b1, d_x1, bid, tid, s_rows, s_psum);
        gbar();
        if (bid == 0) lif_scan_layer(d_x1, d_sp1, v1, i1, r1, tid, s_x);
        gbar();
        gemm_phase(d_sp1, W2, b2, d_x2, bid, tid, s_rows, s_psum);
        gbar();
        if (bid == 0) lif_scan_layer(d_x2, traces + (size_t)t * (BB * HN),
                                     v2, i2, r2, tid, s_x);
    }
}

// ---------------- hidden reduction + policy logits ----------------
__global__ void __launch_bounds__(256) k_logits(const float* __restrict__ traces,
                                                const float* __restrict__ Wp,
                                                const float* __restrict__ bp,
                                                float* __restrict__ out)
{
    __shared__ float hrow[HN];
    const int b = blockIdx.x;
    const int tid = threadIdx.x;
    float s = 0.f;
    for (int t = 0; t < TT; ++t)
        s += traces[(size_t)t * (BB * HN) + b * HN + tid];
    hrow[tid] = __fdiv_rn(s, 100.0f);
    __syncthreads();
    if (tid < 5) {
        float acc = 0.f;
        for (int h = 0; h < HN; ++h)
            acc += hrow[h] * __ldg(Wp + h * 5 + tid);
        out[b * 5 + tid] = acc + __ldg(bp + tid);
    }
}

// ---------------- launch ----------------
extern "C" void kernel_launch(void* const* d_in, const int* in_sizes, int n_in,
                              void* d_out, int out_size) {
    const float* spikes = (const float*)d_in[0];
    const float* adj    = (const float*)d_in[1];
    const float* W0     = (const float*)d_in[2];
    const float* b0     = (const float*)d_in[3];
    const float* W1     = (const float*)d_in[4];
    const float* b1     = (const float*)d_in[5];
    const float* W2     = (const float*)d_in[6];
    const float* b2     = (const float*)d_in[7];
    const float* Wp     = (const float*)d_in[8];
    const float* bp     = (const float*)d_in[9];
    float* out = (float*)d_out;        // [logits(64*5) | traces(100*64*256)]
    float* traces = out + BB * 5;

    const int smem_bytes = (16384 + 512 + 2048) * (int)sizeof(float);
    cudaFuncSetAttribute(k_persist_slow, cudaFuncAttributeMaxDynamicSharedMemorySize,
                         smem_bytes);

    float* gA  = nullptr; cudaGetSymbolAddress((void**)&gA,  d_gA);
    float* g   = nullptr; cudaGetSymbolAddress((void**)&g,   d_g);
    float* x0p = nullptr; cudaGetSymbolAddress((void**)&x0p, d_x0p);
    float* x0  = nullptr; cudaGetSymbolAddress((void**)&x0,  d_x0);

    // zero traces + reset speculation flag (independent of GEMMs)
    k_zero_traces<<<400, 256>>>(traces);
    // g = spikes @ adj   (K=4096 split 4) — f32x2 SGEMM
    k_sgemm_part<<<dim3(NN / 32, 4), 256>>>(spikes, adj, gA, NN, NN / 4, NN);
    k_reduce_g<<<256, 256>>>();
    // x0 partials = g @ W0   (K=4096 split 32) — f32x2 SGEMM, full-chip
    k_sgemm_part<<<dim3(HN / 32, 32), 256>>>(g, W0, x0p, NN, NN / 32, HN);
    // finalize x0 + analytic no-spike validation (max-bound, rigorous)
    k_validate<<<65, 256>>>(b0, b1, b2);
    // exact fallback (early-exits when validation passed)
    k_persist_slow<<<GBLK, 256, smem_bytes>>>(x0, W1, b1, W2, b2, traces);
    // hidden reduction + policy head
    k_logits<<<BB, 256>>>(traces, Wp, bp, out);
}

// round 5
// speedup vs baseline: 1.4454x; 1.4454x over previous
#include <cuda_runtime.h>
#include <cuda_bf16.h>

// ---------------- problem constants ----------------
#define HN    256
#define BB    64
#define NN    4096
#define TT    100
#define GBLK  32

#define V_REST_C   (-70.0f)
#define V_RESET_C  (-75.0f)
#define V_THRESH_C (-55.0f)
// rigorous no-spike bound: v_max - V_REST <= 5*max(0,max_input); spike needs
// input >= 3.0; use 2.9 for float slop (actual max ~1.8)
#define X_LIMIT    2.9f

#define KSPLIT1   16      // GEMM1 k-split (spikes@adj)
#define KSPLIT2   64      // GEMM2 k-split (g@W0)

// ---------------- static device scratch ----------------
__device__ float d_gA[KSPLIT1 * BB * NN];   // GEMM1 partials (16 MB)
__device__ float d_g[BB * NN];              // g = spikes@adj
__device__ float d_x0p[KSPLIT2 * BB * HN];  // GEMM2 partials (4 MB)
__device__ float d_x0[BB * HN];             // x0_pre = g@W0 + b0
__device__ float d_sp0[BB * HN];
__device__ float d_sp1[BB * HN];
__device__ float d_x1[BB * HN];
__device__ float d_x2[BB * HN];
__device__ unsigned d_barcount;
__device__ unsigned d_bargen;
__device__ unsigned d_need_slow;

// ---------------- f32x2 helpers (PTX-only packed IEEE-RN FMA) ----------------
__device__ __forceinline__ void fma2(unsigned long long& acc,
                                     unsigned long long a,
                                     unsigned long long b) {
    asm("fma.rn.f32x2 %0, %1, %2, %0;" : "+l"(acc) : "l"(a), "l"(b));
}
__device__ __forceinline__ unsigned long long dup2(float a) {
    unsigned long long r;
    asm("mov.b64 %0, {%1, %1};" : "=l"(r) : "f"(a));
    return r;
}
__device__ __forceinline__ void unpack2(unsigned long long p, float& lo, float& hi) {
    asm("mov.b64 {%0, %1}, %2;" : "=f"(lo), "=f"(hi) : "l"(p));
}

// ---------------- LIF micro-step ----------------
__device__ __forceinline__ void lif_step(float& v, float& isyn, float& refr,
                                         float ib, float& sp) {
    const bool  in_refr = refr > 0.0f;
    const float isyn_u  = isyn + (ib - isyn * 0.2f);
    const float v_u     = v + (isyn_u - (v - V_REST_C)) * 0.05f;
    const bool  spike   = (!in_refr) && (v_u >= V_THRESH_C);
    v    = in_refr ? v    : (spike ? V_RESET_C : v_u);
    isyn = in_refr ? isyn : isyn_u;
    refr = in_refr ? (refr - 1.0f) : (spike ? 2.0f : refr);
    sp   = spike ? 1.0f : 0.0f;
}

// ---------------- grid barrier ----------------
__device__ __forceinline__ void gbar() {
    __syncthreads();
    if (threadIdx.x == 0) {
        __threadfence();
        unsigned gen = *((volatile unsigned*)&d_bargen);
        if (atomicAdd(&d_barcount, 1u) == GBLK - 1u) {
            d_barcount = 0u;
            __threadfence();
            atomicAdd(&d_bargen, 1u);
        } else {
            while (*((volatile unsigned*)&d_bargen) == gen) { }
        }
        __threadfence();
    }
    __syncthreads();
}

// ---------------- f32x2 SGEMM: Cpart[gy] = A[64,Kchunk] @ B[Kchunk,N] -------
// BM=64, BN=256, BK=16, 128 threads, thread tile 8M x 16N (64 f32x2 accs).
// Pairs along N: B operand = natural 8B shared pairs (conflict-free LDS.64);
// A duplicated in registers via mov.b64 (ALU pipe, no extra LDS traffic).
__global__ void __launch_bounds__(128) k_sgemm_f32x2(
    const float* __restrict__ A, const float* __restrict__ B,
    float* __restrict__ Cp, int lda, int Kchunk, int N)
{
    __shared__ __align__(16) float As[16][64];    // [k][m]
    __shared__ __align__(16) float Bs[16][256];   // [k][n]
    const int tid = threadIdx.x;
    const int n0  = blockIdx.x * 256;
    const int k0  = blockIdx.y * Kchunk;
    const int mg  = tid >> 4;        // 0..7  -> rows mg*8..mg*8+7
    const int ng  = tid & 15;        // 0..15 -> col pairs ng*2 + 32p

    unsigned long long acc[8][8];
#pragma unroll
    for (int i = 0; i < 8; ++i)
#pragma unroll
        for (int p = 0; p < 8; ++p) acc[i][p] = 0ull;

    // loader indices
    const int lm = tid & 63;         // A row
    const int lh = tid >> 6;         // 0..1 -> k offset 8*lh
    const int bk = tid >> 3;         // 0..15 B row
    const int bc = (tid & 7) * 32;   // B col group (32 floats per thread)

    for (int kt = 0; kt < Kchunk; kt += 16) {
        // stage A [64][16] transposed -> As[k][m]
        {
            const float* ap = A + (size_t)lm * lda + (k0 + kt + lh * 8);
            float4 a0 = *(const float4*)(ap);
            float4 a1 = *(const float4*)(ap + 4);
            const int kb = lh * 8;
            As[kb + 0][lm] = a0.x;  As[kb + 1][lm] = a0.y;
            As[kb + 2][lm] = a0.z;  As[kb + 3][lm] = a0.w;
            As[kb + 4][lm] = a1.x;  As[kb + 5][lm] = a1.y;
            As[kb + 6][lm] = a1.z;  As[kb + 7][lm] = a1.w;
        }
        // stage B [16][256] direct
        {
            const float* bpg = B + (size_t)(k0 + kt + bk) * N + (n0 + bc);
#pragma unroll
            for (int w = 0; w < 8; ++w)
                *(float4*)&Bs[bk][bc + 4 * w] = *(const float4*)(bpg + 4 * w);
        }
        __syncthreads();

#pragma unroll 4
        for (int k = 0; k < 16; ++k) {
            float4 alo = *(const float4*)&As[k][mg * 8];
            float4 ahi = *(const float4*)&As[k][mg * 8 + 4];
            unsigned long long ad[8];
            ad[0] = dup2(alo.x); ad[1] = dup2(alo.y);
            ad[2] = dup2(alo.z); ad[3] = dup2(alo.w);
            ad[4] = dup2(ahi.x); ad[5] = dup2(ahi.y);
            ad[6] = dup2(ahi.z); ad[7] = dup2(ahi.w);
            unsigned long long bp_[8];
#pragma unroll
            for (int p = 0; p < 8; ++p)
                bp_[p] = *(const unsigned long long*)&Bs[k][ng * 2 + 32 * p];
#pragma unroll
            for (int i = 0; i < 8; ++i)
#pragma unroll
                for (int p = 0; p < 8; ++p)
                    fma2(acc[i][p], ad[i], bp_[p]);
        }
        __syncthreads();
    }

    float* C = Cp + (size_t)blockIdx.y * (64ull * (size_t)N);
#pragma unroll
    for (int i = 0; i < 8; ++i) {
        const size_t row = (size_t)(mg * 8 + i) * N;
#pragma unroll
        for (int p = 0; p < 8; ++p) {
            float lo, hi;
            unpack2(acc[i][p], lo, hi);
            float2 o = {lo, hi};
            *(float2*)&C[row + n0 + ng * 2 + 32 * p] = o;
        }
    }
}

// g = sum of KSPLIT1 partials
__global__ void __launch_bounds__(256) k_reduce_g() {
    int i = blockIdx.x * blockDim.x + threadIdx.x;
    int stride = gridDim.x * blockDim.x;
    for (; i < BB * NN; i += stride) {
        float s = 0.f;
#pragma unroll
        for (int p = 0; p < KSPLIT1; ++p) s += d_gA[p * (BB * NN) + i];
        d_g[i] = s;
    }
}

// ---------------- zero traces + reset flag ----------------
__global__ void __launch_bounds__(256) k_zero_traces(float* __restrict__ traces) {
    if (blockIdx.x == 0 && threadIdx.x == 0) d_need_slow = 0u;
    const float4 z = {0.f, 0.f, 0.f, 0.f};
    float4* t4 = (float4*)traces;
    int i = blockIdx.x * blockDim.x + threadIdx.x;
    int stride = gridDim.x * blockDim.x;
    const int n4 = (TT * BB * HN) / 4;
    for (; i < n4; i += stride) t4[i] = z;
}

// ---------------- validate: reduce x0 partials + analytic no-spike checks ---
__global__ void __launch_bounds__(256) k_validate(const float* __restrict__ b0,
                                                  const float* __restrict__ b1,
                                                  const float* __restrict__ b2)
{
    const int tid = threadIdx.x;
    int bad;
    if (blockIdx.x < 64) {
        const int i = blockIdx.x * 256 + tid;
        float s = 0.f;
#pragma unroll
        for (int p = 0; p < KSPLIT2; ++p) s += d_x0p[p * (BB * HN) + i];
        s += __ldg(b0 + tid);
        d_x0[i] = s;
        bad = (s >= X_LIMIT);
    } else {
        bad = (__ldg(b1 + tid) >= X_LIMIT) || (__ldg(b2 + tid) >= X_LIMIT);
    }
    if (__syncthreads_or(bad) && tid == 0) atomicOr(&d_need_slow, 1u);
}

// ---------------- exact fallback (verified round-2 path) ----------------
__device__ __forceinline__ int stage_to_smem(const float* __restrict__ src,
                                             float* __restrict__ s_x, int tid) {
    const float4* s4 = (const float4*)src;
    float4* dd = (float4*)s_x;
    int flag = 0;
#pragma unroll
    for (int it = 0; it < 16; ++it) {
        int i = tid + it * 256;
        float4 v = __ldcg(s4 + i);
        flag |= (v.x != 0.f) | (v.y != 0.f) | (v.z != 0.f) | (v.w != 0.f);
        dd[i] = v;
    }
    return flag;
}

__device__ __forceinline__ void gemm_phase(const float* __restrict__ sp,
                                           const float* __restrict__ W,
                                           const float* __restrict__ bias,
                                           float* __restrict__ xout,
                                           int bid, int tid,
                                           float* s_rows, float* s_psum) {
    int flag = 0;
#pragma unroll
    for (int it = 0; it < 2; ++it) {
        int i = tid + it * 256;
        float v = __ldcg(sp + bid * 512 + i);
        flag |= (v != 0.f);
        s_rows[i] = v;
    }
    const int tx = tid & 63;
    const int ty = tid >> 6;
    const int c0 = tx * 4;
    const int kb = ty * 64;
    const int any = __syncthreads_or(flag);

    if (any) {
        float4 a0 = {0.f, 0.f, 0.f, 0.f}, a1 = {0.f, 0.f, 0.f, 0.f};
        const float* s0 = s_rows + kb;
        const float* s1 = s_rows + 256 + kb;
#pragma unroll 8
        for (int k = 0; k < 64; ++k) {
            float4 ww = __ldg((const float4*)(W + (size_t)(kb + k) * 256 + c0));
            float u0 = s0[k], u1 = s1[k];
            a0.x += u0 * ww.x; a0.y += u0 * ww.y; a0.z += u0 * ww.z; a0.w += u0 * ww.w;
            a1.x += u1 * ww.x; a1.y += u1 * ww.y; a1.z += u1 * ww.z; a1.w += u1 * ww.w;
        }
        *(float4*)&s_psum[(ty * 2 + 0) * 256 + c0] = a0;
        *(float4*)&s_psum[(ty * 2 + 1) * 256 + c0] = a1;
        __syncthreads();
        if (ty == 0) {
#pragma unroll
            for (int r = 0; r < 2; ++r) {
                float4 p0 = *(float4*)&s_psum[(0 + r) * 256 + c0];
                float4 p1 = *(float4*)&s_psum[(2 + r) * 256 + c0];
                float4 p2 = *(float4*)&s_psum[(4 + r) * 256 + c0];
                float4 p3 = *(float4*)&s_psum[(6 + r) * 256 + c0];
                float4 bbv = __ldg((const float4*)(bias + c0));
                float4 o;
                o.x = ((p0.x + p1.x) + (p2.x + p3.x)) + bbv.x;
                o.y = ((p0.y + p1.y) + (p2.y + p3.y)) + bbv.y;
                o.z = ((p0.z + p1.z) + (p2.z + p3.z)) + bbv.z;
                o.w = ((p0.w + p1.w) + (p2.w + p3.w)) + bbv.w;
                *(float4*)(xout + (size_t)(bid * 2 + r) * 256 + c0) = o;
            }
        }
        __syncthreads();
    } else {
        if (ty == 0) {
            float4 bbv = __ldg((const float4*)(bias + c0));
#pragma unroll
            for (int r = 0; r < 2; ++r)
                *(float4*)(xout + (size_t)(bid * 2 + r) * 256 + c0) = bbv;
        }
        __syncthreads();
    }
}

__device__ __forceinline__ void lif_scan_layer(const float* __restrict__ xin,
                                               float* __restrict__ spout,
                                               float& v, float& isyn, float& refr,
                                               int tid, float* s_x) {
    int flag = stage_to_smem(xin, s_x, tid);
    flag |= (v != V_REST_C) | (isyn != 0.f) | (refr != 0.f);
    const int any = __syncthreads_or(flag);
    if (any) {
        float nxt = s_x[tid];
#pragma unroll 4
        for (int b = 0; b < 64; ++b) {
            float ib = nxt;
            if (b < 63) nxt = s_x[(b + 1) * 256 + tid];
            float sp;
            lif_step(v, isyn, refr, ib, sp);
            spout[b * 256 + tid] = sp;
        }
    } else {
        float4 z = {0.f, 0.f, 0.f, 0.f};
        float4* o4 = (float4*)spout;
#pragma unroll
        for (int it = 0; it < 16; ++it) o4[tid + it * 256] = z;
    }
    __syncthreads();
}

__global__ void __launch_bounds__(256) k_persist_slow(
    const float* __restrict__ x0pre,
    const float* __restrict__ W1, const float* __restrict__ b1,
    const float* __restrict__ W2, const float* __restrict__ b2,
    float* __restrict__ traces)
{
    if (atomicOr(&d_need_slow, 0u) == 0u) return;

    extern __shared__ float sh[];
    float* s_x    = sh;
    float* s_rows = sh + 16384;
    float* s_psum = sh + 16896;
    const int tid = threadIdx.x;
    const int bid = blockIdx.x;

    float v0 = V_REST_C, i0 = 0.f, r0 = 0.f;
    float v1 = V_REST_C, i1 = 0.f, r1 = 0.f;
    float v2 = V_REST_C, i2 = 0.f, r2 = 0.f;

    for (int t = 0; t < TT; ++t) {
        if (bid == 0) {
            float nxt = __ldg(x0pre + tid);
#pragma unroll 4
            for (int b = 0; b < 64; ++b) {
                float ib = nxt;
                if (b < 63) nxt = __ldg(x0pre + (b + 1) * 256 + tid);
                float sp;
                lif_step(v0, i0, r0, ib, sp);
                d_sp0[b * 256 + tid] = sp;
            }
        }
        gbar();
        gemm_phase(d_sp0, W1, b1, d_x1, bid, tid, s_rows, s_psum);
        gbar();
        if (bid == 0) lif_scan_layer(d_x1, d_sp1, v1, i1, r1, tid, s_x);
        gbar();
        gemm_phase(d_sp1, W2, b2, d_x2, bid, tid, s_rows, s_psum);
        gbar();
        if (bid == 0) lif_scan_layer(d_x2, traces + (size_t)t * (BB * HN),
                                     v2, i2, r2, tid, s_x);
    }
}

// ---------------- hidden reduction + policy logits ----------------
__global__ void __launch_bounds__(256) k_logits(const float* __restrict__ traces,
                                                const float* __restrict__ Wp,
                                                const float* __restrict__ bp,
                                                float* __restrict__ out)
{
    __shared__ float hrow[HN];
    const int b = blockIdx.x;
    const int tid = threadIdx.x;
    float s = 0.f;
    for (int t = 0; t < TT; ++t)
        s += traces[(size_t)t * (BB * HN) + b * HN + tid];
    hrow[tid] = __fdiv_rn(s, 100.0f);
    __syncthreads();
    if (tid < 5) {
        float acc = 0.f;
        for (int h = 0; h < HN; ++h)
            acc += hrow[h] * __ldg(Wp + h * 5 + tid);
        out[b * 5 + tid] = acc + __ldg(bp + tid);
    }
}

// ---------------- launch ----------------
extern "C" void kernel_launch(void* const* d_in, const int* in_sizes, int n_in,
                              void* d_out, int out_size) {
    const float* spikes = (const float*)d_in[0];
    const float* adj    = (const float*)d_in[1];
    const float* W0     = (const float*)d_in[2];
    const float* b0     = (const float*)d_in[3];
    const float* W1     = (const float*)d_in[4];
    const float* b1     = (const float*)d_in[5];
    const float* W2     = (const float*)d_in[6];
    const float* b2     = (const float*)d_in[7];
    const float* Wp     = (const float*)d_in[8];
    const float* bp     = (const float*)d_in[9];
    float* out = (float*)d_out;        // [logits(64*5) | traces(100*64*256)]
    float* traces = out + BB * 5;

    const int smem_bytes = (16384 + 512 + 2048) * (int)sizeof(float);
    cudaFuncSetAttribute(k_persist_slow, cudaFuncAttributeMaxDynamicSharedMemorySize,
                         smem_bytes);

    float* gA  = nullptr; cudaGetSymbolAddress((void**)&gA,  d_gA);
    float* g   = nullptr; cudaGetSymbolAddress((void**)&g,   d_g);
    float* x0p = nullptr; cudaGetSymbolAddress((void**)&x0p, d_x0p);
    float* x0  = nullptr; cudaGetSymbolAddress((void**)&x0,  d_x0);

    // zero traces + reset speculation flag
    k_zero_traces<<<400, 256>>>(traces);
    // g partials = spikes @ adj   (K=4096 split 16) — FMA-bound f32x2 SGEMM
    k_sgemm_f32x2<<<dim3(NN / 256, KSPLIT1), 128>>>(spikes, adj, gA,
                                                    NN, NN / KSPLIT1, NN);
    k_reduce_g<<<256, 256>>>();
    // x0 partials = g @ W0   (K=4096 split 64)
    k_sgemm_f32x2<<<dim3(HN / 256, KSPLIT2), 128>>>(g, W0, x0p,
                                                    NN, NN / KSPLIT2, HN);
    // finalize x0 + analytic no-spike validation
    k_validate<<<65, 256>>>(b0, b1, b2);
    // exact fallback (early-exits when validation passed)
    k_persist_slow<<<GBLK, 256, smem_bytes>>>(x0, W1, b1, W2, b2, traces);
    // hidden reduction + policy head
    k_logits<<<BB, 256>>>(traces, Wp, bp, out);
}

// round 7
// speedup vs baseline: 1.5661x; 1.0835x over previous
#include <cuda_runtime.h>
#include <cuda_bf16.h>
#include <cstdint>

// ---------------- problem constants ----------------
#define HN    256
#define BB    64
#define NN    4096
#define TT    100
#define GBLK  32

#define V_REST_C   (-70.0f)
#define V_RESET_C  (-75.0f)
#define V_THRESH_C (-55.0f)
// rigorous no-spike bound: v_max - V_REST <= 5*max(0,max_input); spike needs
// input >= 3.0; use 2.9 for float slop (actual max ~1.8). x0 is EXACT fp32.
#define X_LIMIT    2.9f

#define KS1 16      // GEMM1 k-split (Kchunk 256)
#define KS2 32      // GEMM2 k-split (Kchunk 128)

// ---------------- static device scratch ----------------
__device__ float d_gA[KS1 * BB * NN];        // GEMM1 partials (16 MB)
__device__ float d_g[BB * NN];               // g = spikes@adj
__device__ float d_x0p[KS2 * BB * HN];       // GEMM2 partials (2 MB)
__device__ float d_x0[BB * HN];              // x0_pre = g@W0 + b0
__device__ float d_sp0[BB * HN];
__device__ float d_sp1[BB * HN];
__device__ float d_x1[BB * HN];
__device__ float d_x2[BB * HN];
__device__ unsigned d_barcount;
__device__ unsigned d_bargen;
__device__ unsigned d_need_slow;

// ---------------- f32x2 helpers (PTX-only packed IEEE-RN FMA) ----------------
__device__ __forceinline__ void fma2(unsigned long long& acc,
                                     unsigned long long a, unsigned long long b) {
    asm("fma.rn.f32x2 %0, %1, %2, %0;" : "+l"(acc) : "l"(a), "l"(b));
}
__device__ __forceinline__ unsigned long long dup2(float a) {
    unsigned long long r;
    asm("mov.b64 %0, {%1, %1};" : "=l"(r) : "f"(a));
    return r;
}
__device__ __forceinline__ void unpack2(unsigned long long p, float& lo, float& hi) {
    asm("mov.b64 {%0, %1}, %2;" : "=f"(lo), "=f"(hi) : "l"(p));
}

// ---------------- LIF micro-step ----------------
__device__ __forceinline__ void lif_step(float& v, float& isyn, float& refr,
                                         float ib, float& sp) {
    const bool  in_refr = refr > 0.0f;
    const float isyn_u  = isyn + (ib - isyn * 0.2f);
    const float v_u     = v + (isyn_u - (v - V_REST_C)) * 0.05f;
    const bool  spike   = (!in_refr) && (v_u >= V_THRESH_C);
    v    = in_refr ? v    : (spike ? V_RESET_C : v_u);
    isyn = in_refr ? isyn : isyn_u;
    refr = in_refr ? (refr - 1.0f) : (spike ? 2.0f : refr);
    sp   = spike ? 1.0f : 0.0f;
}

// ---------------- grid barrier ----------------
__device__ __forceinline__ void gbar() {
    __syncthreads();
    if (threadIdx.x == 0) {
        __threadfence();
        unsigned gen = *((volatile unsigned*)&d_bargen);
        if (atomicAdd(&d_barcount, 1u) == GBLK - 1u) {
            d_barcount = 0u;
            __threadfence();
            atomicAdd(&d_bargen, 1u);
        } else {
            while (*((volatile unsigned*)&d_bargen) == gen) { }
        }
        __threadfence();
    }
    __syncthreads();
}

// ---------------- f32x2 SGEMM: Cpart[gy] = A[64,Kchunk] @ B[Kchunk,N] -------
// BM=64, BN=256, BK=16, 256 threads, thread tile 8M x 8N (32 f32x2 accs).
// Warp = one M-group (A reads broadcast); B pairs lane-consecutive LDS.64.
// A duplicated in registers via mov.b64 (ALU pipe).
__global__ void __launch_bounds__(256) k_sgemm_f32x2(
    const float* __restrict__ A, const float* __restrict__ B,
    float* __restrict__ Cp, int lda, int Kchunk, int N)
{
    __shared__ __align__(16) float As[16][64];    // [k][m]
    __shared__ __align__(16) float Bs[16][256];   // [k][n]
    const int tid = threadIdx.x;
    const int n0  = blockIdx.x * 256;
    const int k0  = blockIdx.y * Kchunk;
    const int mg  = tid >> 5;        // 0..7  -> rows mg*8..mg*8+7 (warp-uniform)
    const int ng  = tid & 31;        // 0..31 -> col pairs ng*2 + 64*p

    unsigned long long acc[8][4];
#pragma unroll
    for (int i = 0; i < 8; ++i)
#pragma unroll
        for (int p = 0; p < 4; ++p) acc[i][p] = 0ull;

    // loader indices
    const int lm = tid & 63;         // A row
    const int lh = tid >> 6;         // 0..3 -> k offset 4*lh
    const int bk = tid >> 4;         // 0..15 B row
    const int bc = (tid & 15) * 16;  // B col group (16 floats per thread)

    for (int kt = 0; kt < Kchunk; kt += 16) {
        // stage A [64][16] transposed -> As[k][m]
        {
            float4 a0 = *(const float4*)(A + (size_t)lm * lda + (k0 + kt + lh * 4));
            const int kb = lh * 4;
            As[kb + 0][lm] = a0.x;  As[kb + 1][lm] = a0.y;
            As[kb + 2][lm] = a0.z;  As[kb + 3][lm] = a0.w;
        }
        // stage B [16][256] direct
        {
            const float* bpg = B + (size_t)(k0 + kt + bk) * N + (n0 + bc);
#pragma unroll
            for (int w = 0; w < 4; ++w)
                *(float4*)&Bs[bk][bc + 4 * w] = *(const float4*)(bpg + 4 * w);
        }
        __syncthreads();

#pragma unroll 4
        for (int k = 0; k < 16; ++k) {
            float4 alo = *(const float4*)&As[k][mg * 8];
            float4 ahi = *(const float4*)&As[k][mg * 8 + 4];
            unsigned long long ad[8];
            ad[0] = dup2(alo.x); ad[1] = dup2(alo.y);
            ad[2] = dup2(alo.z); ad[3] = dup2(alo.w);
            ad[4] = dup2(ahi.x); ad[5] = dup2(ahi.y);
            ad[6] = dup2(ahi.z); ad[7] = dup2(ahi.w);
            unsigned long long bp_[4];
#pragma unroll
            for (int p = 0; p < 4; ++p)
                bp_[p] = *(const unsigned long long*)&Bs[k][ng * 2 + 64 * p];
#pragma unroll
            for (int i = 0; i < 8; ++i)
#pragma unroll
                for (int p = 0; p < 4; ++p)
                    fma2(acc[i][p], ad[i], bp_[p]);
        }
        __syncthreads();
    }

    float* C = Cp + (size_t)blockIdx.y * (64ull * (size_t)N);
#pragma unroll
    for (int i = 0; i < 8; ++i) {
        const size_t row = (size_t)(mg * 8 + i) * N;
#pragma unroll
        for (int p = 0; p < 4; ++p) {
            float lo, hi;
            unpack2(acc[i][p], lo, hi);
            float2 o = {lo, hi};
            *(float2*)&C[row + n0 + ng * 2 + 64 * p] = o;
        }
    }
}

// g = sum of KS1 partials
__global__ void __launch_bounds__(256) k_reduce_g() {
    int i = blockIdx.x * blockDim.x + threadIdx.x;
    const int stride = gridDim.x * blockDim.x;
    for (; i < BB * NN; i += stride) {
        float s = 0.f;
#pragma unroll
        for (int p = 0; p < KS1; ++p) s += d_gA[p * (BB * NN) + i];
        d_g[i] = s;
    }
}

// ---------------- zero traces + reset flag ----------------
__global__ void __launch_bounds__(256) k_zero_traces(float* __restrict__ traces) {
    if (blockIdx.x == 0 && threadIdx.x == 0) d_need_slow = 0u;
    const float4 z = {0.f, 0.f, 0.f, 0.f};
    float4* t4 = (float4*)traces;
    int i = blockIdx.x * blockDim.x + threadIdx.x;
    const int stride = gridDim.x * blockDim.x;
    const int n4 = (TT * BB * HN) / 4;
    for (; i < n4; i += stride) t4[i] = z;
}

// ---------------- validate: reduce x0 partials + analytic no-spike checks ---
__global__ void __launch_bounds__(256) k_validate(const float* __restrict__ b0,
                                                  const float* __restrict__ b1,
                                                  const float* __restrict__ b2)
{
    const int tid = threadIdx.x;
    int bad;
    if (blockIdx.x < 64) {
        const int i = blockIdx.x * 256 + tid;
        float s = 0.f;
#pragma unroll
        for (int p = 0; p < KS2; ++p) s += d_x0p[p * (BB * HN) + i];
        s += __ldg(b0 + (i & 255));
        d_x0[i] = s;
        bad = (s >= X_LIMIT);
    } else {
        bad = (__ldg(b1 + tid) >= X_LIMIT) || (__ldg(b2 + tid) >= X_LIMIT);
    }
    if (__syncthreads_or(bad) && tid == 0) atomicOr(&d_need_slow, 1u);
}

// ---------------- exact fallback persistent path (guarded) ----------------
__device__ __forceinline__ int stage_to_smem(const float* __restrict__ src,
                                             float* __restrict__ s_x, int tid) {
    const float4* s4 = (const float4*)src;
    float4* dd = (float4*)s_x;
    int flag = 0;
#pragma unroll
    for (int it = 0; it < 16; ++it) {
        const int i = tid + it * 256;
        float4 v = __ldcg(s4 + i);
        flag |= (v.x != 0.f) | (v.y != 0.f) | (v.z != 0.f) | (v.w != 0.f);
        dd[i] = v;
    }
    return flag;
}

__device__ __forceinline__ void gemm_phase(const float* __restrict__ sp,
                                           const float* __restrict__ W,
                                           const float* __restrict__ bias,
                                           float* __restrict__ xout,
                                           int bid, int tid,
                                           float* s_rows, float* s_psum) {
    int flag = 0;
#pragma unroll
    for (int it = 0; it < 2; ++it) {
        const int i = tid + it * 256;
        const float v = __ldcg(sp + bid * 512 + i);
        flag |= (v != 0.f);
        s_rows[i] = v;
    }
    const int tx = tid & 63;
    const int ty = tid >> 6;
    const int c0 = tx * 4;
    const int kb = ty * 64;
    const int any = __syncthreads_or(flag);

    if (any) {
        float4 a0 = {0.f, 0.f, 0.f, 0.f}, a1 = {0.f, 0.f, 0.f, 0.f};
        const float* s0 = s_rows + kb;
        const float* s1 = s_rows + 256 + kb;
#pragma unroll 8
        for (int k = 0; k < 64; ++k) {
            float4 ww = __ldg((const float4*)(W + (size_t)(kb + k) * 256 + c0));
            const float u0 = s0[k], u1 = s1[k];
            a0.x += u0 * ww.x; a0.y += u0 * ww.y; a0.z += u0 * ww.z; a0.w += u0 * ww.w;
            a1.x += u1 * ww.x; a1.y += u1 * ww.y; a1.z += u1 * ww.z; a1.w += u1 * ww.w;
        }
        *(float4*)&s_psum[(ty * 2 + 0) * 256 + c0] = a0;
        *(float4*)&s_psum[(ty * 2 + 1) * 256 + c0] = a1;
        __syncthreads();
        if (ty == 0) {
#pragma unroll
            for (int r = 0; r < 2; ++r) {
                float4 p0 = *(float4*)&s_psum[(0 + r) * 256 + c0];
                float4 p1 = *(float4*)&s_psum[(2 + r) * 256 + c0];
                float4 p2 = *(float4*)&s_psum[(4 + r) * 256 + c0];
                float4 p3 = *(float4*)&s_psum[(6 + r) * 256 + c0];
                float4 bbv = __ldg((const float4*)(bias + c0));
                float4 o;
                o.x = ((p0.x + p1.x) + (p2.x + p3.x)) + bbv.x;
                o.y = ((p0.y + p1.y) + (p2.y + p3.y)) + bbv.y;
                o.z = ((p0.z + p1.z) + (p2.z + p3.z)) + bbv.z;
                o.w = ((p0.w + p1.w) + (p2.w + p3.w)) + bbv.w;
                *(float4*)(xout + (size_t)(bid * 2 + r) * 256 + c0) = o;
            }
        }
        __syncthreads();
    } else {
        if (ty == 0) {
            float4 bbv = __ldg((const float4*)(bias + c0));
#pragma unroll
            for (int r = 0; r < 2; ++r)
                *(float4*)(xout + (size_t)(bid * 2 + r) * 256 + c0) = bbv;
        }
        __syncthreads();
    }
}

__device__ __forceinline__ void lif_scan_layer(const float* __restrict__ xin,
                                               float* __restrict__ spout,
                                               float& v, float& isyn, float& refr,
                                               int tid, float* s_x) {
    int flag = stage_to_smem(xin, s_x, tid);
    flag |= (v != V_REST_C) | (isyn != 0.f) | (refr != 0.f);
    const int any = __syncthreads_or(flag);
    if (any) {
        float nxt = s_x[tid];
#pragma unroll 4
        for (int b = 0; b < 64; ++b) {
            const float ib = nxt;
            if (b < 63) nxt = s_x[(b + 1) * 256 + tid];
            float sp;
            lif_step(v, isyn, refr, ib, sp);
            spout[b * 256 + tid] = sp;
        }
    } else {
        const float4 z = {0.f, 0.f, 0.f, 0.f};
        float4* o4 = (float4*)spout;
#pragma unroll
        for (int it = 0; it < 16; ++it) o4[tid + it * 256] = z;
    }
    __syncthreads();
}

__global__ void __launch_bounds__(256) k_persist_slow(
    const float* __restrict__ x0pre,
    const float* __restrict__ W1, const float* __restrict__ b1,
    const float* __restrict__ W2, const float* __restrict__ b2,
    float* __restrict__ traces)
{
    if (atomicOr(&d_need_slow, 0u) == 0u) return;

    extern __shared__ float sh[];
    float* s_x    = sh;
    float* s_rows = sh + 16384;
    float* s_psum = sh + 16896;
    const int tid = threadIdx.x;
    const int bid = blockIdx.x;

    float v0 = V_REST_C, i0 = 0.f, r0 = 0.f;
    float v1 = V_REST_C, i1 = 0.f, r1 = 0.f;
    float v2 = V_REST_C, i2 = 0.f, r2 = 0.f;

    for (int t = 0; t < TT; ++t) {
        if (bid == 0) {
            float nxt = __ldg(x0pre + tid);
#pragma unroll 4
            for (int b = 0; b < 64; ++b) {
                const float ib = nxt;
                if (b < 63) nxt = __ldg(x0pre + (b + 1) * 256 + tid);
                float sp;
                lif_step(v0, i0, r0, ib, sp);
                d_sp0[b * 256 + tid] = sp;
            }
        }
        gbar();
        gemm_phase(d_sp0, W1, b1, d_x1, bid, tid, s_rows, s_psum);
        gbar();
        if (bid == 0) lif_scan_layer(d_x1, d_sp1, v1, i1, r1, tid, s_x);
        gbar();
        gemm_phase(d_sp1, W2, b2, d_x2, bid, tid, s_rows, s_psum);
        gbar();
        if (bid == 0) lif_scan_layer(d_x2, traces + (size_t)t * (BB * HN),
                                     v2, i2, r2, tid, s_x);
    }
}

// ---------------- hidden reduction + policy logits ----------------
__global__ void __launch_bounds__(256) k_logits(const float* __restrict__ traces,
                                                const float* __restrict__ Wp,
                                                const float* __restrict__ bp,
                                                float* __restrict__ out)
{
    __shared__ float hrow[HN];
    const int b = blockIdx.x;
    const int tid = threadIdx.x;
    float s = 0.f;
    for (int t = 0; t < TT; ++t)
        s += traces[(size_t)t * (BB * HN) + b * HN + tid];
    hrow[tid] = __fdiv_rn(s, 100.0f);
    __syncthreads();
    if (tid < 5) {
        float acc = 0.f;
        for (int h = 0; h < HN; ++h)
            acc += hrow[h] * __ldg(Wp + h * 5 + tid);
        out[b * 5 + tid] = acc + __ldg(bp + tid);
    }
}

// ---------------- launch ----------------
extern "C" void kernel_launch(void* const* d_in, const int* in_sizes, int n_in,
                              void* d_out, int out_size) {
    const float* spikes = (const float*)d_in[0];
    const float* adj    = (const float*)d_in[1];
    const float* W0     = (const float*)d_in[2];
    const float* b0     = (const float*)d_in[3];
    const float* W1     = (const float*)d_in[4];
    const float* b1     = (const float*)d_in[5];
    const float* W2     = (const float*)d_in[6];
    const float* b2     = (const float*)d_in[7];
    const float* Wp     = (const float*)d_in[8];
    const float* bp     = (const float*)d_in[9];
    float* out = (float*)d_out;        // [logits(64*5) | traces(100*64*256)]
    float* traces = out + BB * 5;

    const int smem_slow = (16384 + 512 + 2048) * (int)sizeof(float);
    cudaFuncSetAttribute(k_persist_slow, cudaFuncAttributeMaxDynamicSharedMemorySize,
                         smem_slow);

    void* p;
    cudaGetSymbolAddress(&p, d_gA);   float* gA  = (float*)p;
    cudaGetSymbolAddress(&p, d_g);    float* g   = (float*)p;
    cudaGetSymbolAddress(&p, d_x0p);  float* x0p = (float*)p;
    cudaGetSymbolAddress(&p, d_x0);   float* x0  = (float*)p;

    // zero traces + reset speculation flag
    k_zero_traces<<<400, 256>>>(traces);
    // g partials = spikes @ adj   (K=4096 split 16, Kchunk 256)
    k_sgemm_f32x2<<<dim3(NN / 256, KS1), 256>>>(spikes, adj, gA, NN, NN / KS1, NN);
    k_reduce_g<<<256, 256>>>();
    // x0 partials = g @ W0   (K=4096 split 32, Kchunk 128)
    k_sgemm_f32x2<<<dim3(HN / 256, KS2), 256>>>(g, W0, x0p, NN, NN / KS2, HN);
    // finalize x0 + rigorous no-spike validation
    k_validate<<<65, 256>>>(b0, b1, b2);
    // exact persistent simulation (early-exits when certified spike-free)
    k_persist_slow<<<GBLK, 256, smem_slow>>>(x0, W1, b1, W2, b2, traces);
    // hidden reduction + policy head
    k_logits<<<BB, 256>>>(traces, Wp, bp, out);
}

// round 8
// speedup vs baseline: 1.8154x; 1.1592x over previous
#include <cuda_runtime.h>
#include <cuda_bf16.h>
#include <cstdint>

// ---------------- problem constants ----------------
#define HN    256
#define BB    64
#define NN    4096
#define TT    100
#define GBLK  32

#define V_REST_C   (-70.0f)
#define V_RESET_C  (-75.0f)
#define V_THRESH_C (-55.0f)
// no-spike bound: v_max - V_REST <= 5*max(0,max_input); spike needs input>=3.0.
// 2.5 leaves >=0.5 margin over worst-case fp32 reduction-order divergence (~0.15)
// between our exact-fp32 x0 and the reference's fp32 x0. Actual max(x0) ~ 1.8.
#define X_LIMIT    2.5f

#define KS1 16      // GEMM1 k-split (Kchunk 256)
#define KS2 64      // GEMM2 k-split (Kchunk 64)

// ---------------- static device scratch ----------------
__device__ float d_gA[KS1 * BB * NN];        // GEMM1 partials (16 MB)
__device__ float d_x0p[KS2 * BB * HN];       // GEMM2 partials (4 MB)
__device__ float d_x0[BB * HN];              // x0_pre = g@W0 + b0
__device__ float d_sp0[BB * HN];
__device__ float d_sp1[BB * HN];
__device__ float d_x1[BB * HN];
__device__ float d_x2[BB * HN];
__device__ unsigned d_barcount;
__device__ unsigned d_bargen;
__device__ unsigned d_need_slow;

// ---------------- f32x2 helpers (PTX-only packed IEEE-RN FMA) ----------------
__device__ __forceinline__ void fma2(unsigned long long& acc,
                                     unsigned long long a, unsigned long long b) {
    asm("fma.rn.f32x2 %0, %1, %2, %0;" : "+l"(acc) : "l"(a), "l"(b));
}
__device__ __forceinline__ unsigned long long dup2(float a) {
    unsigned long long r;
    asm("mov.b64 %0, {%1, %1};" : "=l"(r) : "f"(a));
    return r;
}
__device__ __forceinline__ void unpack2(unsigned long long p, float& lo, float& hi) {
    asm("mov.b64 {%0, %1}, %2;" : "=f"(lo), "=f"(hi) : "l"(p));
}

// ---------------- cp.async helpers ----------------
__device__ __forceinline__ void cpasync16(uint32_t dst, const void* src) {
    asm volatile("cp.async.cg.shared.global [%0], [%1], 16;"
                 :: "r"(dst), "l"(src));
}
__device__ __forceinline__ void cpasync_commit() {
    asm volatile("cp.async.commit_group;" ::: "memory");
}
template <int N>
__device__ __forceinline__ void cpasync_wait() {
    asm volatile("cp.async.wait_group %0;" :: "n"(N) : "memory");
}

// ---------------- LIF micro-step ----------------
__device__ __forceinline__ void lif_step(float& v, float& isyn, float& refr,
                                         float ib, float& sp) {
    const bool  in_refr = refr > 0.0f;
    const float isyn_u  = isyn + (ib - isyn * 0.2f);
    const float v_u     = v + (isyn_u - (v - V_REST_C)) * 0.05f;
    const bool  spike   = (!in_refr) && (v_u >= V_THRESH_C);
    v    = in_refr ? v    : (spike ? V_RESET_C : v_u);
    isyn = in_refr ? isyn : isyn_u;
    refr = in_refr ? (refr - 1.0f) : (spike ? 2.0f : refr);
    sp   = spike ? 1.0f : 0.0f;
}

// ---------------- grid barrier ----------------
__device__ __forceinline__ void gbar() {
    __syncthreads();
    if (threadIdx.x == 0) {
        __threadfence();
        unsigned gen = *((volatile unsigned*)&d_bargen);
        if (atomicAdd(&d_barcount, 1u) == GBLK - 1u) {
            d_barcount = 0u;
            __threadfence();
            atomicAdd(&d_bargen, 1u);
        } else {
            while (*((volatile unsigned*)&d_bargen) == gen) { }
        }
        __threadfence();
    }
    __syncthreads();
}

// ---------------- A prefetch: optionally sums nsum slabs (fused reduce) -----
__device__ __forceinline__ float4 load_a_sum(const float* __restrict__ A,
                                             size_t off, int nsum, int stride) {
    float4 a = __ldg((const float4*)(A + off));
    for (int p = 1; p < nsum; ++p) {
        float4 t = __ldg((const float4*)(A + (size_t)p * stride + off));
        a.x += t.x; a.y += t.y; a.z += t.z; a.w += t.w;
    }
    return a;
}

// ---------------- pipelined f32x2 SGEMM -------------------------------------
// Cpart[gy] = (sum_slabs A)[64,Kchunk] @ B[Kchunk,N]
// BM=64, BN=256, BK=16, 256 threads, thread tile 8M x 8N (32 f32x2 accs).
// B staged via cp.async (double buffer, 1 tile ahead); A via register prefetch.
__global__ void __launch_bounds__(256) k_sgemm_pipe(
    const float* __restrict__ A, const float* __restrict__ B,
    float* __restrict__ Cp, int lda, int Kchunk, int N, int nsum, int slabstride)
{
    __shared__ __align__(16) float As[2][16][64];    // [buf][k][m]
    __shared__ __align__(16) float Bs[2][16][256];   // [buf][k][n]
    const int tid = threadIdx.x;
    const int n0  = blockIdx.x * 256;
    const int k0  = blockIdx.y * Kchunk;
    const int mg  = tid >> 5;        // warp id -> M rows mg*8.. (warp-uniform)
    const int ng  = tid & 31;        // lane -> col pairs ng*2 + 64*p
    const int lm  = tid & 63;        // A loader row
    const int lh  = tid >> 6;        // A loader k-quad (0..3)
    const int bk  = tid >> 4;        // B loader row (0..15)
    const int bc  = (tid & 15) * 16; // B loader col base
    const int T   = Kchunk >> 4;

    unsigned long long acc[8][4];
#pragma unroll
    for (int i = 0; i < 8; ++i)
#pragma unroll
        for (int p = 0; p < 4; ++p) acc[i][p] = 0ull;

    // prologue: A(0) -> regs, B(0) -> cp.async buf0
    float4 areg = load_a_sum(A, (size_t)lm * lda + (k0 + lh * 4), nsum, slabstride);
    {
        uint32_t bdst = (uint32_t)__cvta_generic_to_shared(&Bs[0][bk][bc]);
        const float* bp = B + (size_t)(k0 + bk) * N + (n0 + bc);
#pragma unroll
        for (int w = 0; w < 4; ++w) cpasync16(bdst + 16 * w, bp + 4 * w);
        cpasync_commit();
    }

    for (int t = 0; t < T; ++t) {
        const int cur = t & 1;
        // store A(t) (regs loaded one iteration ago; latency covered by compute)
        {
            const int kb = lh * 4;
            As[cur][kb + 0][lm] = areg.x;  As[cur][kb + 1][lm] = areg.y;
            As[cur][kb + 2][lm] = areg.z;  As[cur][kb + 3][lm] = areg.w;
        }
        if (t + 1 < T) {
            // prefetch A(t+1) regs + issue B(t+1) cp.async into the other buffer
            areg = load_a_sum(A, (size_t)lm * lda + (k0 + (t + 1) * 16 + lh * 4),
                              nsum, slabstride);
            uint32_t bdst = (uint32_t)__cvta_generic_to_shared(&Bs[cur ^ 1][bk][bc]);
            const float* bp = B + (size_t)(k0 + (t + 1) * 16 + bk) * N + (n0 + bc);
#pragma unroll
            for (int w = 0; w < 4; ++w) cpasync16(bdst + 16 * w, bp + 4 * w);
            cpasync_commit();
            cpasync_wait<1>();       // tile t's B is resident
        } else {
            cpasync_wait<0>();
        }
        __syncthreads();

#pragma unroll 4
        for (int k = 0; k < 16; ++k) {
            float4 alo = *(const float4*)&As[cur][k][mg * 8];
            float4 ahi = *(const float4*)&As[cur][k][mg * 8 + 4];
            unsigned long long ad[8];
            ad[0] = dup2(alo.x); ad[1] = dup2(alo.y);
            ad[2] = dup2(alo.z); ad[3] = dup2(alo.w);
            ad[4] = dup2(ahi.x); ad[5] = dup2(ahi.y);
            ad[6] = dup2(ahi.z); ad[7] = dup2(ahi.w);
            unsigned long long bp_[4];
#pragma unroll
            for (int p = 0; p < 4; ++p)
                bp_[p] = *(const unsigned long long*)&Bs[cur][k][ng * 2 + 64 * p];
#pragma unroll
            for (int i = 0; i < 8; ++i)
#pragma unroll
                for (int p = 0; p < 4; ++p)
                    fma2(acc[i][p], ad[i], bp_[p]);
        }
        __syncthreads();
    }

    float* C = Cp + (size_t)blockIdx.y * (64ull * (size_t)N);
#pragma unroll
    for (int i = 0; i < 8; ++i) {
        const size_t row = (size_t)(mg * 8 + i) * N;
#pragma unroll
        for (int p = 0; p < 4; ++p) {
            float lo, hi;
            unpack2(acc[i][p], lo, hi);
            float2 o = {lo, hi};
            *(float2*)&C[row + n0 + ng * 2 + 64 * p] = o;
        }
    }
}

// ---------------- zero traces + reset flag ----------------
__global__ void __launch_bounds__(256) k_zero_traces(float* __restrict__ traces) {
    if (blockIdx.x == 0 && threadIdx.x == 0) d_need_slow = 0u;
    const float4 z = {0.f, 0.f, 0.f, 0.f};
    float4* t4 = (float4*)traces;
    int i = blockIdx.x * blockDim.x + threadIdx.x;
    const int stride = gridDim.x * blockDim.x;
    const int n4 = (TT * BB * HN) / 4;
    for (; i < n4; i += stride) t4[i] = z;
}

// ---------------- validate: reduce x0 partials + analytic no-spike checks ---
__global__ void __launch_bounds__(256) k_validate(const float* __restrict__ b0,
                                                  const float* __restrict__ b1,
                                                  const float* __restrict__ b2)
{
    const int tid = threadIdx.x;
    int bad;
    if (blockIdx.x < 64) {
        const int i = blockIdx.x * 256 + tid;
        float s = 0.f;
#pragma unroll 8
        for (int p = 0; p < KS2; ++p) s += d_x0p[p * (BB * HN) + i];
        s += __ldg(b0 + (i & 255));
        d_x0[i] = s;
        bad = (s >= X_LIMIT);
    } else {
        bad = (__ldg(b1 + tid) >= X_LIMIT) || (__ldg(b2 + tid) >= X_LIMIT);
    }
    if (__syncthreads_or(bad) && tid == 0) atomicOr(&d_need_slow, 1u);
}

// ---------------- exact fallback persistent path (guarded) ----------------
__device__ __forceinline__ int stage_to_smem(const float* __restrict__ src,
                                             float* __restrict__ s_x, int tid) {
    const float4* s4 = (const float4*)src;
    float4* dd = (float4*)s_x;
    int flag = 0;
#pragma unroll
    for (int it = 0; it < 16; ++it) {
        const int i = tid + it * 256;
        float4 v = __ldcg(s4 + i);
        flag |= (v.x != 0.f) | (v.y != 0.f) | (v.z != 0.f) | (v.w != 0.f);
        dd[i] = v;
    }
    return flag;
}

__device__ __forceinline__ void gemm_phase(const float* __restrict__ sp,
                                           const float* __restrict__ W,
                                           const float* __restrict__ bias,
                                           float* __restrict__ xout,
                                           int bid, int tid,
                                           float* s_rows, float* s_psum) {
    int flag = 0;
#pragma unroll
    for (int it = 0; it < 2; ++it) {
        const int i = tid + it * 256;
        const float v = __ldcg(sp + bid * 512 + i);
        flag |= (v != 0.f);
        s_rows[i] = v;
    }
    const int tx = tid & 63;
    const int ty = tid >> 6;
    const int c0 = tx * 4;
    const int kb = ty * 64;
    const int any = __syncthreads_or(flag);

    if (any) {
        float4 a0 = {0.f, 0.f, 0.f, 0.f}, a1 = {0.f, 0.f, 0.f, 0.f};
        const float* s0 = s_rows + kb;
        const float* s1 = s_rows + 256 + kb;
#pragma unroll 8
        for (int k = 0; k < 64; ++k) {
            float4 ww = __ldg((const float4*)(W + (size_t)(kb + k) * 256 + c0));
            const float u0 = s0[k], u1 = s1[k];
            a0.x += u0 * ww.x; a0.y += u0 * ww.y; a0.z += u0 * ww.z; a0.w += u0 * ww.w;
            a1.x += u1 * ww.x; a1.y += u1 * ww.y; a1.z += u1 * ww.z; a1.w += u1 * ww.w;
        }
        *(float4*)&s_psum[(ty * 2 + 0) * 256 + c0] = a0;
        *(float4*)&s_psum[(ty * 2 + 1) * 256 + c0] = a1;
        __syncthreads();
        if (ty == 0) {
#pragma unroll
            for (int r = 0; r < 2; ++r) {
                float4 p0 = *(float4*)&s_psum[(0 + r) * 256 + c0];
                float4 p1 = *(float4*)&s_psum[(2 + r) * 256 + c0];
                float4 p2 = *(float4*)&s_psum[(4 + r) * 256 + c0];
                float4 p3 = *(float4*)&s_psum[(6 + r) * 256 + c0];
                float4 bbv = __ldg((const float4*)(bias + c0));
                float4 o;
                o.x = ((p0.x + p1.x) + (p2.x + p3.x)) + bbv.x;
                o.y = ((p0.y + p1.y) + (p2.y + p3.y)) + bbv.y;
                o.z = ((p0.z + p1.z) + (p2.z + p3.z)) + bbv.z;
                o.w = ((p0.w + p1.w) + (p2.w + p3.w)) + bbv.w;
                *(float4*)(xout + (size_t)(bid * 2 + r) * 256 + c0) = o;
            }
        }
        __syncthreads();
    } else {
        if (ty == 0) {
            float4 bbv = __ldg((const float4*)(bias + c0));
#pragma unroll
            for (int r = 0; r < 2; ++r)
                *(float4*)(xout + (size_t)(bid * 2 + r) * 256 + c0) = bbv;
        }
        __syncthreads();
    }
}

__device__ __forceinline__ void lif_scan_layer(const float* __restrict__ xin,
                                               float* __restrict__ spout,
                                               float& v, float& isyn, float& refr,
                                               int tid, float* s_x) {
    int flag = stage_to_smem(xin, s_x, tid);
    flag |= (v != V_REST_C) | (isyn != 0.f) | (refr != 0.f);
    const int any = __syncthreads_or(flag);
    if (any) {
        float nxt = s_x[tid];
#pragma unroll 4
        for (int b = 0; b < 64; ++b) {
            const float ib = nxt;
            if (b < 63) nxt = s_x[(b + 1) * 256 + tid];
            float sp;
            lif_step(v, isyn, refr, ib, sp);
            spout[b * 256 + tid] = sp;
        }
    } else {
        const float4 z = {0.f, 0.f, 0.f, 0.f};
        float4* o4 = (float4*)spout;
#pragma unroll
        for (int it = 0; it < 16; ++it) o4[tid + it * 256] = z;
    }
    __syncthreads();
}

__global__ void __launch_bounds__(256) k_persist_slow(
    const float* __restrict__ x0pre,
    const float* __restrict__ W1, const float* __restrict__ b1,
    const float* __restrict__ W2, const float* __restrict__ b2,
    float* __restrict__ traces)
{
    if (atomicOr(&d_need_slow, 0u) == 0u) return;

    extern __shared__ float sh[];
    float* s_x    = sh;
    float* s_rows = sh + 16384;
    float* s_psum = sh + 16896;
    const int tid = threadIdx.x;
    const int bid = blockIdx.x;

    float v0 = V_REST_C, i0 = 0.f, r0 = 0.f;
    float v1 = V_REST_C, i1 = 0.f, r1 = 0.f;
    float v2 = V_REST_C, i2 = 0.f, r2 = 0.f;

    for (int t = 0; t < TT; ++t) {
        if (bid == 0) {
            float nxt = __ldg(x0pre + tid);
#pragma unroll 4
            for (int b = 0; b < 64; ++b) {
                const float ib = nxt;
                if (b < 63) nxt = __ldg(x0pre + (b + 1) * 256 + tid);
                float sp;
                lif_step(v0, i0, r0, ib, sp);
                d_sp0[b * 256 + tid] = sp;
            }
        }
        gbar();
        gemm_phase(d_sp0, W1, b1, d_x1, bid, tid, s_rows, s_psum);
        gbar();
        if (bid == 0) lif_scan_layer(d_x1, d_sp1, v1, i1, r1, tid, s_x);
        gbar();
        gemm_phase(d_sp1, W2, b2, d_x2, bid, tid, s_rows, s_psum);
        gbar();
        if (bid == 0) lif_scan_layer(d_x2, traces + (size_t)t * (BB * HN),
                                     v2, i2, r2, tid, s_x);
    }
}

// ---------------- hidden reduction + policy logits ----------------
__global__ void __launch_bounds__(256) k_logits(const float* __restrict__ traces,
                                                const float* __restrict__ Wp,
                                                const float* __restrict__ bp,
                                                float* __restrict__ out)
{
    __shared__ float hrow[HN];
    const int b = blockIdx.x;
    const int tid = threadIdx.x;
    float s = 0.f;
    for (int t = 0; t < TT; ++t)
        s += traces[(size_t)t * (BB * HN) + b * HN + tid];
    hrow[tid] = __fdiv_rn(s, 100.0f);
    __syncthreads();
    if (tid < 5) {
        float acc = 0.f;
        for (int h = 0; h < HN; ++h)
            acc += hrow[h] * __ldg(Wp + h * 5 + tid);
        out[b * 5 + tid] = acc + __ldg(bp + tid);
    }
}

// ---------------- launch ----------------
extern "C" void kernel_launch(void* const* d_in, const int* in_sizes, int n_in,
                              void* d_out, int out_size) {
    const float* spikes = (const float*)d_in[0];
    const float* adj    = (const float*)d_in[1];
    const float* W0     = (const float*)d_in[2];
    const float* b0     = (const float*)d_in[3];
    const float* W1     = (const float*)d_in[4];
    const float* b1     = (const float*)d_in[5];
    const float* W2     = (const float*)d_in[6];
    const float* b2     = (const float*)d_in[7];
    const float* Wp     = (const float*)d_in[8];
    const float* bp     = (const float*)d_in[9];
    float* out = (float*)d_out;        // [logits(64*5) | traces(100*64*256)]
    float* traces = out + BB * 5;

    const int smem_slow = (16384 + 512 + 2048) * (int)sizeof(float);
    cudaFuncSetAttribute(k_persist_slow, cudaFuncAttributeMaxDynamicSharedMemorySize,
                         smem_slow);

    void* p;
    cudaGetSymbolAddress(&p, d_gA);   float* gA  = (float*)p;
    cudaGetSymbolAddress(&p, d_x0p);  float* x0p = (float*)p;
    cudaGetSymbolAddress(&p, d_x0);   float* x0  = (float*)p;

    // zero traces + reset speculation flag
    k_zero_traces<<<400, 256>>>(traces);
    // GEMM1: g partials = spikes @ adj   (K=4096 split 16, Kchunk 256)
    k_sgemm_pipe<<<dim3(NN / 256, KS1), 256>>>(spikes, adj, gA,
                                               NN, NN / KS1, NN, 1, 0);
    // GEMM2: x0 partials = (sum g partials) @ W0  (K=4096 split 64, Kchunk 64)
    // fused reduce: A-loader sums the KS1 slabs of d_gA
    k_sgemm_pipe<<<dim3(HN / 256, KS2), 256>>>(gA, W0, x0p,
                                               NN, NN / KS2, HN, KS1, BB * NN);
    // finalize x0 + rigorous no-spike validation
    k_validate<<<65, 256>>>(b0, b1, b2);
    // exact persistent simulation (early-exits when certified spike-free)
    k_persist_slow<<<GBLK, 256, smem_slow>>>(x0, W1, b1, W2, b2, traces);
    // hidden reduction + policy head
    k_logits<<<BB, 256>>>(traces, Wp, bp, out);
}

// round 9
// speedup vs baseline: 2.1865x; 1.2044x over previous
#include <cuda_runtime.h>
#include <cuda_bf16.h>
#include <cstdint>

// ---------------- problem constants ----------------
#define HN    256
#define BB    64
#define NN    4096
#define TT    100
#define GBLK  32

#define V_REST_C   (-70.0f)
#define V_RESET_C  (-75.0f)
#define V_THRESH_C (-55.0f)
// no-spike bound: v_max - V_REST <= 5*max(0,max_input); spike needs input>=3.0.
// Exact quantities use 2.5 (>=0.5 margin over fp32 order divergence). The
// split-bf16 tensor x0 gets 2.4 (extra 0.1 budget for split residuals ~1e-3).
#define X_LIMIT_EXACT  2.5f
#define X_LIMIT_TENSOR 2.4f

#define KSM1 8      // mma GEMM1 k-split (Kchunk 512)
#define KSM2 32     // GEMM2 k-split (Kchunk 128) — shared by mma + exact paths
#define KSE1 16     // exact GEMM1 k-split (Kchunk 256)

// ---------------- static device scratch ----------------
__device__ float d_gA[KSE1 * BB * NN];       // GEMM1 partials (16 MB; mma uses 8)
__device__ float d_x0p[KSM2 * BB * HN];      // GEMM2 partials (2 MB)
__device__ float d_x0[BB * HN];
__device__ __nv_bfloat16 d_spH[BB * NN];     // spikes split hi
__device__ __nv_bfloat16 d_spL[BB * NN];     // spikes split lo
__device__ __nv_bfloat16 d_gH[BB * NN];      // g split hi
__device__ __nv_bfloat16 d_gL[BB * NN];      // g split lo
__device__ float d_sp0[BB * HN];
__device__ float d_sp1[BB * HN];
__device__ float d_x1[BB * HN];
__device__ float d_x2[BB * HN];
__device__ unsigned d_barcount;
__device__ unsigned d_bargen;
__device__ unsigned d_need_slow;

// ---------------- helpers ----------------
__device__ __forceinline__ unsigned short f2bf(float x) {
    __nv_bfloat16 h = __float2bfloat16(x);
    return *reinterpret_cast<unsigned short*>(&h);
}
__device__ __forceinline__ float bf2f(unsigned short u) {
    __nv_bfloat16 h = *reinterpret_cast<__nv_bfloat16*>(&u);
    return __bfloat162float(h);
}
__device__ __forceinline__ void fma2(unsigned long long& acc,
                                     unsigned long long a, unsigned long long b) {
    asm("fma.rn.f32x2 %0, %1, %2, %0;" : "+l"(acc) : "l"(a), "l"(b));
}
__device__ __forceinline__ unsigned long long dup2(float a) {
    unsigned long long r;
    asm("mov.b64 %0, {%1, %1};" : "=l"(r) : "f"(a));
    return r;
}
__device__ __forceinline__ void unpack2(unsigned long long p, float& lo, float& hi) {
    asm("mov.b64 {%0, %1}, %2;" : "=f"(lo), "=f"(hi) : "l"(p));
}
__device__ __forceinline__ void cpasync16(uint32_t dst, const void* src) {
    asm volatile("cp.async.cg.shared.global [%0], [%1], 16;" :: "r"(dst), "l"(src));
}
__device__ __forceinline__ void cpasync_commit() {
    asm volatile("cp.async.commit_group;" ::: "memory");
}
template <int N>
__device__ __forceinline__ void cpasync_wait() {
    asm volatile("cp.async.wait_group %0;" :: "n"(N) : "memory");
}
__device__ __forceinline__ void ldmat4(uint32_t* r, uint32_t addr) {
    asm volatile("ldmatrix.sync.aligned.m8n8.x4.shared.b16 {%0,%1,%2,%3}, [%4];"
                 : "=r"(r[0]), "=r"(r[1]), "=r"(r[2]), "=r"(r[3]) : "r"(addr));
}
__device__ __forceinline__ void mma16816(float* c, const uint32_t* a,
                                         uint32_t b0, uint32_t b1) {
    asm volatile(
        "mma.sync.aligned.m16n8k16.row.col.f32.bf16.bf16.f32 "
        "{%0,%1,%2,%3}, {%4,%5,%6,%7}, {%8,%9}, {%0,%1,%2,%3};"
        : "+f"(c[0]), "+f"(c[1]), "+f"(c[2]), "+f"(c[3])
        : "r"(a[0]), "r"(a[1]), "r"(a[2]), "r"(a[3]), "r"(b0), "r"(b1));
}

// ---------------- LIF micro-step ----------------
__device__ __forceinline__ void lif_step(float& v, float& isyn, float& refr,
                                         float ib, float& sp) {
    const bool  in_refr = refr > 0.0f;
    const float isyn_u  = isyn + (ib - isyn * 0.2f);
    const float v_u     = v + (isyn_u - (v - V_REST_C)) * 0.05f;
    const bool  spike   = (!in_refr) && (v_u >= V_THRESH_C);
    v    = in_refr ? v    : (spike ? V_RESET_C : v_u);
    isyn = in_refr ? isyn : isyn_u;
    refr = in_refr ? (refr - 1.0f) : (spike ? 2.0f : refr);
    sp   = spike ? 1.0f : 0.0f;
}

// ---------------- grid barrier ----------------
__device__ __forceinline__ void gbar() {
    __syncthreads();
    if (threadIdx.x == 0) {
        __threadfence();
        unsigned gen = *((volatile unsigned*)&d_bargen);
        if (atomicAdd(&d_barcount, 1u) == GBLK - 1u) {
            d_barcount = 0u;
            __threadfence();
            atomicAdd(&d_bargen, 1u);
        } else {
            while (*((volatile unsigned*)&d_bargen) == gen) { }
        }
        __threadfence();
    }
    __syncthreads();
}

// ---------------- split spikes fp32 -> bf16 hi/lo ----------------
__global__ void __launch_bounds__(256) k_split_spikes(const float* __restrict__ s) {
    const int i4 = blockIdx.x * 256 + threadIdx.x;     // 65536 float4s
    float4 v = __ldg((const float4*)s + i4);
    ushort4 h, l;
    h.x = f2bf(v.x); l.x = f2bf(v.x - bf2f(h.x));
    h.y = f2bf(v.y); l.y = f2bf(v.y - bf2f(h.y));
    h.z = f2bf(v.z); l.z = f2bf(v.z - bf2f(h.z));
    h.w = f2bf(v.w); l.w = f2bf(v.w - bf2f(h.w));
    ((ushort4*)d_spH)[i4] = h;
    ((ushort4*)d_spL)[i4] = l;
}

// ---------------- split-bf16 tensor GEMM --------------------------------
// Cpart[blockIdx.y] = A(hi+lo)[64, Kchunk] @ B_fp32[Kchunk, N] via 3 mma terms.
// BM=64, BN=64, BK=64; 256 threads = 8 warps (4 m16-groups x 2 n32-groups).
// A from pre-split global bf16; B converted fp32->bf16 hi/lo in-kernel.
__global__ void __launch_bounds__(256) k_mma_gemm(
    const __nv_bfloat16* __restrict__ Ah, const __nv_bfloat16* __restrict__ Al,
    const float* __restrict__ B, float* __restrict__ Cp, int N, int Kchunk)
{
    __shared__ __align__(16) __nv_bfloat16 smA[2][64][72];   // [h/l][m][k]
    __shared__ __align__(16) __nv_bfloat16 smB[2][64][72];   // [h/l][n][k]
    const int tid  = threadIdx.x;
    const int warp = tid >> 5, lane = tid & 31;
    const int mw = warp & 3;             // m16 group
    const int nw = warp >> 2;            // n32 group (0..1)
    const int n0 = blockIdx.x * 64;
    const int k0 = blockIdx.y * Kchunk;
    const int T  = Kchunk >> 6;

    float acc[4][4];
#pragma unroll
    for (int j = 0; j < 4; ++j)
#pragma unroll
        for (int c = 0; c < 4; ++c) acc[j][c] = 0.f;

    // ldmatrix lane addressing
    const int lm_m = lane >> 3, lm_r = lane & 7;
    const int a_row  = mw * 16 + (lm_m & 1) * 8 + lm_r;
    const int a_kof  = (lm_m >> 1) * 8;
    const int b_nrow = nw * 32 + (lm_m >> 1) * 8 + lm_r;
    const int b_kof  = (lm_m & 1) * 8;
    const uint32_t aH_ad = (uint32_t)__cvta_generic_to_shared(&smA[0][a_row][a_kof]);
    const uint32_t aL_ad = (uint32_t)__cvta_generic_to_shared(&smA[1][a_row][a_kof]);
    const uint32_t bH_ad = (uint32_t)__cvta_generic_to_shared(&smB[0][b_nrow][b_kof]);
    const uint32_t bL_ad = (uint32_t)__cvta_generic_to_shared(&smB[1][b_nrow][b_kof]);

    // loader indices: A: row tid>>2, seg (tid&3)*16 ; B: k-row tid>>2, nseg (tid&3)*16
    const int ar = tid >> 2, as_ = (tid & 3) * 16;
    const int br = tid >> 2, bs_ = (tid & 3) * 16;

    // prologue prefetch (tile 0)
    uint4 a_h0, a_h1, a_l0, a_l1;
    float4 breg[4];
    {
        const uint4* gh = (const uint4*)(Ah + (size_t)ar * NN + k0 + as_);
        const uint4* gl = (const uint4*)(Al + (size_t)ar * NN + k0 + as_);
        a_h0 = __ldg(gh);     a_h1 = __ldg(gh + 1);
        a_l0 = __ldg(gl);     a_l1 = __ldg(gl + 1);
        const float* bp = B + (size_t)(k0 + br) * N + n0 + bs_;
#pragma unroll
        for (int w = 0; w < 4; ++w) breg[w] = __ldg((const float4*)bp + w);
    }

    for (int t = 0; t < T; ++t) {
        // store staged regs (tile t)
        *(uint4*)&smA[0][ar][as_]     = a_h0;
        *(uint4*)&smA[0][ar][as_ + 8] = a_h1;
        *(uint4*)&smA[1][ar][as_]     = a_l0;
        *(uint4*)&smA[1][ar][as_ + 8] = a_l1;
        {
            const float* bf = (const float*)breg;
#pragma unroll
            for (int j = 0; j < 16; ++j) {
                const float x = bf[j];
                const unsigned short h = f2bf(x);
                const unsigned short l = f2bf(x - bf2f(h));
                smB[0][bs_ + j][br] = *reinterpret_cast<const __nv_bfloat16*>(&h);
                smB[1][bs_ + j][br] = *reinterpret_cast<const __nv_bfloat16*>(&l);
            }
        }
        // prefetch tile t+1
        if (t + 1 < T) {
            const int kt = k0 + (t + 1) * 64;
            const uint4* gh = (const uint4*)(Ah + (size_t)ar * NN + kt + as_);
            const uint4* gl = (const uint4*)(Al + (size_t)ar * NN + kt + as_);
            a_h0 = __ldg(gh);     a_h1 = __ldg(gh + 1);
            a_l0 = __ldg(gl);     a_l1 = __ldg(gl + 1);
            const float* bp = B + (size_t)(kt + br) * N + n0 + bs_;
#pragma unroll
            for (int w = 0; w < 4; ++w) breg[w] = __ldg((const float4*)bp + w);
        }
        __syncthreads();

#pragma unroll
        for (int ks = 0; ks < 4; ++ks) {
            uint32_t aH[4], aL[4], bH0[4], bH1[4], bL0[4], bL1[4];
            ldmat4(aH, aH_ad + ks * 32);
            ldmat4(aL, aL_ad + ks * 32);
            ldmat4(bH0, bH_ad + ks * 32);
            ldmat4(bH1, bH_ad + 16 * 144 + ks * 32);
            ldmat4(bL0, bL_ad + ks * 32);
            ldmat4(bL1, bL_ad + 16 * 144 + ks * 32);
            // j=0,1 from *0 regs; j=2,3 from *1 regs
            mma16816(acc[0], aH, bH0[0], bH0[1]);
            mma16816(acc[1], aH, bH0[2], bH0[3]);
            mma16816(acc[2], aH, bH1[0], bH1[1]);
            mma16816(acc[3], aH, bH1[2], bH1[3]);
            mma16816(acc[0], aH, bL0[0], bL0[1]);
            mma16816(acc[1], aH, bL0[2], bL0[3]);
            mma16816(acc[2], aH, bL1[0], bL1[1]);
            mma16816(acc[3], aH, bL1[2], bL1[3]);
            mma16816(acc[0], aL, bH0[0], bH0[1]);
            mma16816(acc[1], aL, bH0[2], bH0[3]);
            mma16816(acc[2], aL, bH1[0], bH1[1]);
            mma16816(acc[3], aL, bH1[2], bH1[3]);
        }
        __syncthreads();
    }

    // epilogue: write fp32 partial slab
    float* C = Cp + (size_t)blockIdx.y * (64ull * (size_t)N);
    const int g = lane >> 2, tig = lane & 3;
#pragma unroll
    for (int j = 0; j < 4; ++j) {
        const int col = n0 + nw * 32 + j * 8 + tig * 2;
        const int r0 = mw * 16 + g;
        float2 o0 = {acc[j][0], acc[j][1]};
        float2 o1 = {acc[j][2], acc[j][3]};
        *(float2*)&C[(size_t)r0 * N + col]       = o0;
        *(float2*)&C[(size_t)(r0 + 8) * N + col] = o1;
    }
}

// ---------------- reduce 8 mma partials -> g, split to bf16 hi/lo ----------
__global__ void __launch_bounds__(256) k_reduce_split_g() {
    const int i4 = blockIdx.x * 256 + threadIdx.x;     // 65536 float4s
    const float4* src = (const float4*)d_gA;
    float4 s = src[i4];
#pragma unroll
    for (int p = 1; p < KSM1; ++p) {
        float4 t = src[(size_t)p * 65536 + i4];
        s.x += t.x; s.y += t.y; s.z += t.z; s.w += t.w;
    }
    ushort4 h, l;
    h.x = f2bf(s.x); l.x = f2bf(s.x - bf2f(h.x));
    h.y = f2bf(s.y); l.y = f2bf(s.y - bf2f(h.y));
    h.z = f2bf(s.z); l.z = f2bf(s.z - bf2f(h.z));
    h.w = f2bf(s.w); l.w = f2bf(s.w - bf2f(h.w));
    ((ushort4*)d_gH)[i4] = h;
    ((ushort4*)d_gL)[i4] = l;
}

// ---------------- zero traces + reset flag ----------------
__global__ void __launch_bounds__(256) k_zero_traces(float* __restrict__ traces) {
    if (blockIdx.x == 0 && threadIdx.x == 0) d_need_slow = 0u;
    const float4 z = {0.f, 0.f, 0.f, 0.f};
    float4* t4 = (float4*)traces;
    int i = blockIdx.x * blockDim.x + threadIdx.x;
    const int stride = gridDim.x * blockDim.x;
    const int n4 = (TT * BB * HN) / 4;
    for (; i < n4; i += stride) t4[i] = z;
}

// ---------------- validate (parallel slab-sum + no-spike bound) ----------
__global__ void __launch_bounds__(256) k_validate(const float* __restrict__ b0,
                                                  const float* __restrict__ b1,
                                                  const float* __restrict__ b2)
{
    __shared__ float red[128];
    const int tid = threadIdx.x;
    int bad = 0;
    if (blockIdx.x < 128) {
        const int out  = blockIdx.x * 128 + (tid & 127);
        const int half = tid >> 7;
        float s = 0.f;
#pragma unroll
        for (int p = 0; p < KSM2 / 2; ++p)
            s += d_x0p[(size_t)(half * (KSM2 / 2) + p) * (BB * HN) + out];
        if (half) red[tid & 127] = s;
        __syncthreads();
        if (!half) {
            const float tot = s + red[tid] + __ldg(b0 + (out & 255));
            d_x0[out] = tot;
            bad = (tot >= X_LIMIT_TENSOR);
        }
    } else {
        bad = (__ldg(b1 + tid) >= X_LIMIT_EXACT) ||
              (__ldg(b2 + tid) >= X_LIMIT_EXACT);
    }
    if (__syncthreads_or(bad) && tid == 0) atomicOr(&d_need_slow, 1u);
}

// ---------------- exact f32x2 pipelined SGEMM (guarded fallback) ----------
__device__ __forceinline__ float4 load_a_sum(const float* __restrict__ A,
                                             size_t off, int nsum, int stride) {
    float4 a = __ldg((const float4*)(A + off));
    for (int p = 1; p < nsum; ++p) {
        float4 t = __ldg((const float4*)(A + (size_t)p * stride + off));
        a.x += t.x; a.y += t.y; a.z += t.z; a.w += t.w;
    }
    return a;
}

__global__ void __launch_bounds__(256) k_sgemm_pipe(
    const float* __restrict__ A, const float* __restrict__ B,
    float* __restrict__ Cp, int lda, int Kchunk, int N, int nsum, int slabstride)
{
    if (*((volatile unsigned*)&d_need_slow) == 0u) return;
    __shared__ __align__(16) float As[2][16][64];
    __shared__ __align__(16) float Bs[2][16][256];
    const int tid = threadIdx.x;
    const int n0  = blockIdx.x * 256;
    const int k0  = blockIdx.y * Kchunk;
    const int mg  = tid >> 5;
    const int ng  = tid & 31;
    const int lm  = tid & 63;
    const int lh  = tid >> 6;
    const int bk  = tid >> 4;
    const int bc  = (tid & 15) * 16;
    const int T   = Kchunk >> 4;

    unsigned long long acc[8][4];
#pragma unroll
    for (int i = 0; i < 8; ++i)
#pragma unroll
        for (int p = 0; p < 4; ++p) acc[i][p] = 0ull;

    float4 areg = load_a_sum(A, (size_t)lm * lda + (k0 + lh * 4), nsum, slabstride);
    {
        uint32_t bdst = (uint32_t)__cvta_generic_to_shared(&Bs[0][bk][bc]);
        const float* bp = B + (size_t)(k0 + bk) * N + (n0 + bc);
#pragma unroll
        for (int w = 0; w < 4; ++w) cpasync16(bdst + 16 * w, bp + 4 * w);
        cpasync_commit();
    }

    for (int t = 0; t < T; ++t) {
        const int cur = t & 1;
        {
            const int kb = lh * 4;
            As[cur][kb + 0][lm] = areg.x;  As[cur][kb + 1][lm] = areg.y;
            As[cur][kb + 2][lm] = areg.z;  As[cur][kb + 3][lm] = areg.w;
        }
        if (t + 1 < T) {
            areg = load_a_sum(A, (size_t)lm * lda + (k0 + (t + 1) * 16 + lh * 4),
                              nsum, slabstride);
            uint32_t bdst = (uint32_t)__cvta_generic_to_shared(&Bs[cur ^ 1][bk][bc]);
            const float* bp = B + (size_t)(k0 + (t + 1) * 16 + bk) * N + (n0 + bc);
#pragma unroll
            for (int w = 0; w < 4; ++w) cpasync16(bdst + 16 * w, bp + 4 * w);
            cpasync_commit();
            cpasync_wait<1>();
        } else {
            cpasync_wait<0>();
        }
        __syncthreads();

#pragma unroll 4
        for (int k = 0; k < 16; ++k) {
            float4 alo = *(const float4*)&As[cur][k][mg * 8];
            float4 ahi = *(const float4*)&As[cur][k][mg * 8 + 4];
            unsigned long long ad[8];
            ad[0] = dup2(alo.x); ad[1] = dup2(alo.y);
            ad[2] = dup2(alo.z); ad[3] = dup2(alo.w);
            ad[4] = dup2(ahi.x); ad[5] = dup2(ahi.y);
            ad[6] = dup2(ahi.z); ad[7] = dup2(ahi.w);
            unsigned long long bp_[4];
#pragma unroll
            for (int p = 0; p < 4; ++p)
                bp_[p] = *(const unsigned long long*)&Bs[cur][k][ng * 2 + 64 * p];
#pragma unroll
            for (int i = 0; i < 8; ++i)
#pragma unroll
                for (int p = 0; p < 4; ++p)
                    fma2(acc[i][p], ad[i], bp_[p]);
        }
        __syncthreads();
    }

    float* C = Cp + (size_t)blockIdx.y * (64ull * (size_t)N);
#pragma unroll
    for (int i = 0; i < 8; ++i) {
        const size_t row = (size_t)(mg * 8 + i) * N;
#pragma unroll
        for (int p = 0; p < 4; ++p) {
            float lo, hi;
            unpack2(acc[i][p], lo, hi);
            float2 o = {lo, hi};
            *(float2*)&C[row + n0 + ng * 2 + 64 * p] = o;
        }
    }
}

// finalize exact x0 (guarded)
__global__ void __launch_bounds__(256) k_finalize_x0(const float* __restrict__ b0) {
    if (*((volatile unsigned*)&d_need_slow) == 0u) return;
    const int i = blockIdx.x * 256 + threadIdx.x;
    float s = 0.f;
#pragma unroll 8
    for (int p = 0; p < KSM2; ++p) s += d_x0p[(size_t)p * (BB * HN) + i];
    d_x0[i] = s + __ldg(b0 + (i & 255));
}

// ---------------- exact fallback persistent path (guarded) ----------------
__device__ __forceinline__ int stage_to_smem(const float* __restrict__ src,
                                             float* __restrict__ s_x, int tid) {
    const float4* s4 = (const float4*)src;
    float4* dd = (float4*)s_x;
    int flag = 0;
#pragma unroll
    for (int it = 0; it < 16; ++it) {
        const int i = tid + it * 256;
        float4 v = __ldcg(s4 + i);
        flag |= (v.x != 0.f) | (v.y != 0.f) | (v.z != 0.f) | (v.w != 0.f);
        dd[i] = v;
    }
    return flag;
}

__device__ __forceinline__ void gemm_phase(const float* __restrict__ sp,
                                           const float* __restrict__ W,
                                           const float* __restrict__ bias,
                                           float* __restrict__ xout,
                                           int bid, int tid,
                                           float* s_rows, float* s_psum) {
    int flag = 0;
#pragma unroll
    for (int it = 0; it < 2; ++it) {
        const int i = tid + it * 256;
        const float v = __ldcg(sp + bid * 512 + i);
        flag |= (v != 0.f);
        s_rows[i] = v;
    }
    const int tx = tid & 63;
    const int ty = tid >> 6;
    const int c0 = tx * 4;
    const int kb = ty * 64;
    const int any = __syncthreads_or(flag);

    if (any) {
        float4 a0 = {0.f, 0.f, 0.f, 0.f}, a1 = {0.f, 0.f, 0.f, 0.f};
        const float* s0 = s_rows + kb;
        const float* s1 = s_rows + 256 + kb;
#pragma unroll 8
        for (int k = 0; k < 64; ++k) {
            float4 ww = __ldg((const float4*)(W + (size_t)(kb + k) * 256 + c0));
            const float u0 = s0[k], u1 = s1[k];
            a0.x += u0 * ww.x; a0.y += u0 * ww.y; a0.z += u0 * ww.z; a0.w += u0 * ww.w;
            a1.x += u1 * ww.x; a1.y += u1 * ww.y; a1.z += u1 * ww.z; a1.w += u1 * ww.w;
        }
        *(float4*)&s_psum[(ty * 2 + 0) * 256 + c0] = a0;
        *(float4*)&s_psum[(ty * 2 + 1) * 256 + c0] = a1;
        __syncthreads();
        if (ty == 0) {
#pragma unroll
            for (int r = 0; r < 2; ++r) {
                float4 p0 = *(float4*)&s_psum[(0 + r) * 256 + c0];
                float4 p1 = *(float4*)&s_psum[(2 + r) * 256 + c0];
                float4 p2 = *(float4*)&s_psum[(4 + r) * 256 + c0];
                float4 p3 = *(float4*)&s_psum[(6 + r) * 256 + c0];
                float4 bbv = __ldg((const float4*)(bias + c0));
                float4 o;
                o.x = ((p0.x + p1.x) + (p2.x + p3.x)) + bbv.x;
                o.y = ((p0.y + p1.y) + (p2.y + p3.y)) + bbv.y;
                o.z = ((p0.z + p1.z) + (p2.z + p3.z)) + bbv.z;
                o.w = ((p0.w + p1.w) + (p2.w + p3.w)) + bbv.w;
                *(float4*)(xout + (size_t)(bid * 2 + r) * 256 + c0) = o;
            }
        }
        __syncthreads();
    } else {
        if (ty == 0) {
            float4 bbv = __ldg((const float4*)(bias + c0));
#pragma unroll
            for (int r = 0; r < 2; ++r)
                *(float4*)(xout + (size_t)(bid * 2 + r) * 256 + c0) = bbv;
        }
        __syncthreads();
    }
}

__device__ __forceinline__ void lif_scan_layer(const float* __restrict__ xin,
                                               float* __restrict__ spout,
                                               float& v, float& isyn, float& refr,
                                               int tid, float* s_x) {
    int flag = stage_to_smem(xin, s_x, tid);
    flag |= (v != V_REST_C) | (isyn != 0.f) | (refr != 0.f);
    const int any = __syncthreads_or(flag);
    if (any) {
        float nxt = s_x[tid];
#pragma unroll 4
        for (int b = 0; b < 64; ++b) {
            const float ib = nxt;
            if (b < 63) nxt = s_x[(b + 1) * 256 + tid];
            float sp;
            lif_step(v, isyn, refr, ib, sp);
            spout[b * 256 + tid] = sp;
        }
    } else {
        const float4 z = {0.f, 0.f, 0.f, 0.f};
        float4* o4 = (float4*)spout;
#pragma unroll
        for (int it = 0; it < 16; ++it) o4[tid + it * 256] = z;
    }
    __syncthreads();
}

__global__ void __launch_bounds__(256) k_persist_slow(
    const float* __restrict__ x0pre,
    const float* __restrict__ W1, const float* __restrict__ b1,
    const float* __restrict__ W2, const float* __restrict__ b2,
    float* __restrict__ traces)
{
    if (atomicOr(&d_need_slow, 0u) == 0u) return;

    extern __shared__ float sh[];
    float* s_x    = sh;
    float* s_rows = sh + 16384;
    float* s_psum = sh + 16896;
    const int tid = threadIdx.x;
    const int bid = blockIdx.x;

    float v0 = V_REST_C, i0 = 0.f, r0 = 0.f;
    float v1 = V_REST_C, i1 = 0.f, r1 = 0.f;
    float v2 = V_REST_C, i2 = 0.f, r2 = 0.f;

    for (int t = 0; t < TT; ++t) {
        if (bid == 0) {
            float nxt = __ldg(x0pre + tid);
#pragma unroll 4
            for (int b = 0; b < 64; ++b) {
                const float ib = nxt;
                if (b < 63) nxt = __ldg(x0pre + (b + 1) * 256 + tid);
                float sp;
                lif_step(v0, i0, r0, ib, sp);
                d_sp0[b * 256 + tid] = sp;
            }
        }
        gbar();
        gemm_phase(d_sp0, W1, b1, d_x1, bid, tid, s_rows, s_psum);
        gbar();
        if (bid == 0) lif_scan_layer(d_x1, d_sp1, v1, i1, r1, tid, s_x);
        gbar();
        gemm_phase(d_sp1, W2, b2, d_x2, bid, tid, s_rows, s_psum);
        gbar();
        if (bid == 0) lif_scan_layer(d_x2, traces + (size_t)t * (BB * HN),
                                     v2, i2, r2, tid, s_x);
    }
}

// ---------------- hidden reduction + policy logits ----------------
__global__ void __launch_bounds__(256) k_logits(const float* __restrict__ traces,
                                                const float* __restrict__ Wp,
                                                const float* __restrict__ bp,
                                                float* __restrict__ out)
{
    __shared__ float hrow[HN];
    const int b = blockIdx.x;
    const int tid = threadIdx.x;
    float s = 0.f;
    for (int t = 0; t < TT; ++t)
        s += traces[(size_t)t * (BB * HN) + b * HN + tid];
    hrow[tid] = __fdiv_rn(s, 100.0f);
    __syncthreads();
    if (tid < 5) {
        float acc = 0.f;
        for (int h = 0; h < HN; ++h)
            acc += hrow[h] * __ldg(Wp + h * 5 + tid);
        out[b * 5 + tid] = acc + __ldg(bp + tid);
    }
}

// ---------------- launch ----------------
extern "C" void kernel_launch(void* const* d_in, const int* in_sizes, int n_in,
                              void* d_out, int out_size) {
    const float* spikes = (const float*)d_in[0];
    const float* adj    = (const float*)d_in[1];
    const float* W0     = (const float*)d_in[2];
    const float* b0     = (const float*)d_in[3];
    const float* W1     = (const float*)d_in[4];
    const float* b1     = (const float*)d_in[5];
    const float* W2     = (const float*)d_in[6];
    const float* b2     = (const float*)d_in[7];
    const float* Wp     = (const float*)d_in[8];
    const float* bp     = (const float*)d_in[9];
    float* out = (float*)d_out;        // [logits(64*5) | traces(100*64*256)]
    float* traces = out + BB * 5;

    const int smem_slow = (16384 + 512 + 2048) * (int)sizeof(float);
    cudaFuncSetAttribute(k_persist_slow, cudaFuncAttributeMaxDynamicSharedMemorySize,
                         smem_slow);

    void* p;
    cudaGetSymbolAddress(&p, d_gA);   float* gA  = (float*)p;
    cudaGetSymbolAddress(&p, d_x0p);  float* x0p = (float*)p;
    cudaGetSymbolAddress(&p, d_x0);   float* x0  = (float*)p;
    cudaGetSymbolAddress(&p, d_spH);  __nv_bfloat16* spH = (__nv_bfloat16*)p;
    cudaGetSymbolAddress(&p, d_spL);  __nv_bfloat16* spL = (__nv_bfloat16*)p;
    cudaGetSymbolAddress(&p, d_gH);   __nv_bfloat16* gH  = (__nv_bfloat16*)p;
    cudaGetSymbolAddress(&p, d_gL);   __nv_bfloat16* gL  = (__nv_bfloat16*)p;

    // zero traces + reset flag; split spikes
    k_zero_traces<<<400, 256>>>(traces);
    k_split_spikes<<<256, 256>>>(spikes);
    // tensor GEMM1: g partials(8) = spikes(split) @ adj
    k_mma_gemm<<<dim3(NN / 64, KSM1), 256>>>(spH, spL, adj, gA, NN, NN / KSM1);
    // reduce partials -> g, split to bf16
    k_reduce_split_g<<<256, 256>>>();
    // tensor GEMM2: x0 partials(32) = g(split) @ W0
    k_mma_gemm<<<dim3(HN / 64, KSM2), 256>>>(gH, gL, W0, x0p, HN, NN / KSM2);
    // finalize approx x0 + rigorous no-spike validation
    k_validate<<<129, 256>>>(b0, b1, b2);
    // guarded exact recompute (early-exit unless validation tripped)
    k_sgemm_pipe<<<dim3(NN / 256, KSE1), 256>>>(spikes, adj, gA,
                                                NN, NN / KSE1, NN, 1, 0);
    k_sgemm_pipe<<<dim3(HN / 256, KSM2), 256>>>(gA, W0, x0p,
                                                NN, NN / KSM2, HN, KSE1, BB * NN);
    k_finalize_x0<<<64, 256>>>(b0);
    // exact persistent simulation (early-exits when certified spike-free)
    k_persist_slow<<<GBLK, 256, smem_slow>>>(x0, W1, b1, W2, b2, traces);
    // hidden reduction + policy head
    k_logits<<<BB, 256>>>(traces, Wp, bp, out);
}